// round 6
// baseline (speedup 1.0000x reference)
#include <cuda_runtime.h>
#include <math.h>
#include <stdint.h>

// Problem constants
#define BB 32
#define TT 512
#define EE 256
#define HH 256
#define GG 1024          // 4*H
#define CC 20
#define MM (BB * TT)     // 16384

// ---------------- device scratch (allocation-free rule: static __device__) --------------
__device__ float g_xp_f[(size_t)MM * GG];   // 64 MB
__device__ float g_xp_b[(size_t)MM * GG];   // 64 MB
__device__ float g_out_f[(size_t)MM * HH];  // 16 MB
__device__ float g_out_b[(size_t)MM * HH];  // 16 MB
__device__ float g_logits[(size_t)MM * CC];
__device__ float g_llh[BB];

// persistent-scan state
__device__ float g_h[2][2][HH][BB];         // [dir][parity][j][b_sorted]
__device__ int   g_flag[2][64];             // per-direction per-CTA step flags
__device__ int   g_perm[BB];                // sorted(batch) -> original batch
__device__ int   g_Lsorted[BB];             // lengths, descending
__device__ int   g_Lmax;

// GEMM compaction
__device__ int   g_rows[MM];                // packed (b<<16)|t for t < seq_len[b]
__device__ int   g_nrows;

// ---------------- kernel 0: setup ----------------
__global__ __launch_bounds__(256)
void setup_kernel(const int* __restrict__ seq_len)
{
    __shared__ int off_s[BB + 1];
    int tid = threadIdx.x;

    // zero h buffers (2*2*256*32 = 32768 floats) and flags
    for (int i = tid; i < 2 * 2 * HH * BB; i += 256)
        (&g_h[0][0][0][0])[i] = 0.f;
    if (tid < 64) { g_flag[0][tid] = 0; g_flag[1][tid] = 0; }

    if (tid == 0) {
        int L[BB], p[BB];
        for (int i = 0; i < BB; i++) { L[i] = seq_len[i]; p[i] = i; }
        // stable insertion sort, descending by L
        for (int i = 1; i < BB; i++) {
            int kl = L[i], kp = p[i];
            int j = i - 1;
            while (j >= 0 && L[j] < kl) { L[j + 1] = L[j]; p[j + 1] = p[j]; j--; }
            L[j + 1] = kl; p[j + 1] = kp;
        }
        for (int i = 0; i < BB; i++) { g_perm[i] = p[i]; g_Lsorted[i] = L[i]; }
        g_Lmax = L[0];
        // prefix offsets in ORIGINAL batch order for row compaction
        int off = 0;
        for (int b = 0; b < BB; b++) { off_s[b] = off; off += seq_len[b]; }
        off_s[BB] = off;
        g_nrows = off;
    }
    __syncthreads();

    // fill compacted row list: thread group (b, r) writes rows t = r, r+8, ...
    int b = tid >> 3, r = tid & 7;
    int off = off_s[b];
    int L = off_s[b + 1] - off;
    for (int t = r; t < L; t += 8)
        g_rows[off + t] = (b << 16) | t;
}

// ---------------- kernel 1: xp = gather(emb, x[, reversed]) @ Wih^T + bias -------------
// Compacted M (only t < seq_len rows). Tile 128x128, BK=8, 256 threads, 8x8 per thread.
__global__ __launch_bounds__(256)
void gemm_xp(const int* __restrict__ x, const int* __restrict__ seq_len,
             const float* __restrict__ emb, const float* __restrict__ Wih,
             const float* __restrict__ bias, int rev)
{
    const int BM = 128, BN = 128, BK = 8;
    __shared__ float As[BK][BM];
    __shared__ float Bs[BK][BN];
    __shared__ int tok[BM];
    __shared__ int orow[BM];

    int nrows = g_nrows;
    int m0 = blockIdx.y * BM;
    if (m0 >= nrows) return;

    float* __restrict__ xp = rev ? g_xp_b : g_xp_f;

    int tid = threadIdx.x;                 // 256
    int n0 = blockIdx.x * BN;

    if (tid < BM) {
        int m = m0 + tid;
        if (m < nrows) {
            int pk = g_rows[m];
            int b = pk >> 16, t = pk & 0xFFFF;
            int tp = rev ? (seq_len[b] - 1 - t) : t;   // t < L by construction
            tok[tid]  = x[b * TT + tp];
            orow[tid] = b * TT + t;
        } else {
            tok[tid] = 0;
            orow[tid] = -1;
        }
    }
    __syncthreads();

    int tx = tid & 15, ty = tid >> 4;
    int am = tid >> 1, ak = (tid & 1) * 4;
    int bn = tid >> 1, bk = (tid & 1) * 4;

    float acc[8][8];
#pragma unroll
    for (int i = 0; i < 8; i++)
#pragma unroll
        for (int j = 0; j < 8; j++) acc[i][j] = 0.f;

    for (int k0 = 0; k0 < EE; k0 += BK) {
        float4 av = *reinterpret_cast<const float4*>(
            &emb[(size_t)tok[am] * EE + k0 + ak]);
        float4 bv = *reinterpret_cast<const float4*>(
            &Wih[(size_t)(n0 + bn) * EE + k0 + bk]);
        __syncthreads();   // previous tile fully consumed
        As[ak + 0][am] = av.x; As[ak + 1][am] = av.y;
        As[ak + 2][am] = av.z; As[ak + 3][am] = av.w;
        Bs[bk + 0][bn] = bv.x; Bs[bk + 1][bn] = bv.y;
        Bs[bk + 2][bn] = bv.z; Bs[bk + 3][bn] = bv.w;
        __syncthreads();

#pragma unroll
        for (int kk = 0; kk < BK; kk++) {
            float a[8], b[8];
            *reinterpret_cast<float4*>(&a[0]) =
                *reinterpret_cast<const float4*>(&As[kk][ty * 8]);
            *reinterpret_cast<float4*>(&a[4]) =
                *reinterpret_cast<const float4*>(&As[kk][ty * 8 + 4]);
            *reinterpret_cast<float4*>(&b[0]) =
                *reinterpret_cast<const float4*>(&Bs[kk][tx * 8]);
            *reinterpret_cast<float4*>(&b[4]) =
                *reinterpret_cast<const float4*>(&Bs[kk][tx * 8 + 4]);
#pragma unroll
            for (int i = 0; i < 8; i++)
#pragma unroll
                for (int j = 0; j < 8; j++) acc[i][j] += a[i] * b[j];
        }
    }

    float bj[8];
#pragma unroll
    for (int j = 0; j < 8; j++) bj[j] = bias[n0 + tx * 8 + j];
#pragma unroll
    for (int i = 0; i < 8; i++) {
        int om = orow[ty * 8 + i];
        if (om >= 0) {
            size_t row = (size_t)om * GG + n0 + tx * 8;
            float4 v0, v1;
            v0.x = acc[i][0] + bj[0]; v0.y = acc[i][1] + bj[1];
            v0.z = acc[i][2] + bj[2]; v0.w = acc[i][3] + bj[3];
            v1.x = acc[i][4] + bj[4]; v1.y = acc[i][5] + bj[5];
            v1.z = acc[i][6] + bj[6]; v1.w = acc[i][7] + bj[7];
            *reinterpret_cast<float4*>(&xp[row]) = v0;
            *reinterpret_cast<float4*>(&xp[row + 4]) = v1;
        }
    }
}

// ---------------- kernel 2: persistent batched LSTM scan --------------------------------
// 128 CTAs: dir = bid>>6, ci = bid&63. CTA owns hidden units j in [ci*4, ci*4+4)
// (16 gate rows, 16KB of Whh in SMEM, k-major, for the whole scan).
// Warp w owns batches [4w, 4w+4) -> finished batches skip as whole warps.
// h exchange via g_h double buffer + per-CTA flag grid barrier (per direction).
__global__ __launch_bounds__(256)
void lstm_scan2(const float* __restrict__ Whh_f, const float* __restrict__ Whh_b)
{
    extern __shared__ float sm[];
    float* Ws   = sm;                    // [256][16]  Ws[k*16 + lrow], lrow = q*4+u
    float* hs   = sm + 256 * 16;         // [256][32]  hs[k*32 + b]
    float* pbuf = sm + 256 * 16 + 256 * 32;  // [8][16][32]
    __shared__ int perm_s[BB];
    __shared__ int Ls[BB];

    int dir = blockIdx.x >> 6;
    int ci  = blockIdx.x & 63;
    int tid = threadIdx.x;

    const float* __restrict__ xp  = dir ? g_xp_b : g_xp_f;
    const float* __restrict__ Whh = dir ? Whh_b : Whh_f;
    float* __restrict__ out       = dir ? g_out_b : g_out_f;

    if (tid < BB) { perm_s[tid] = g_perm[tid]; Ls[tid] = g_Lsorted[tid]; }
    int Lmax = g_Lmax;

    // ---- fill weight slice: 16 rows x 64 k4 chunks ----
    for (int i = tid; i < 16 * 64; i += 256) {
        int lrow = i & 15, k4 = i >> 4;
        int q = lrow >> 2, u = lrow & 3;
        int grow = q * 256 + ci * 4 + u;
        float4 w = *reinterpret_cast<const float4*>(&Whh[(size_t)grow * 256 + k4 * 4]);
        Ws[(k4 * 4 + 0) * 16 + lrow] = w.x;
        Ws[(k4 * 4 + 1) * 16 + lrow] = w.y;
        Ws[(k4 * 4 + 2) * 16 + lrow] = w.z;
        Ws[(k4 * 4 + 3) * 16 + lrow] = w.w;
    }
    __syncthreads();

    // GEMM roles: warp bg (4 batches), lane: ks = k-slice of 32, rowg = 4-row group
    int bg   = tid >> 5;
    int lane = tid & 31;
    int ks   = lane >> 2;
    int rowg = lane & 3;
    // cell roles (tid < 128): b_cell 0..31, u_cell 0..3
    int b_cell = tid >> 2;
    int u_cell = tid & 3;

    float c_state = 0.f;
    int A = BB;

    const float4* W4 = reinterpret_cast<const float4*>(Ws);  // [k][4] float4
    const float4* H4 = reinterpret_cast<const float4*>(hs);  // [k][8] float4

    for (int t = 0; t < Lmax; t++) {
        while (A > 0 && Ls[A - 1] <= t) A--;
        int pw = t & 1, pr = pw ^ 1;

        // ---- fill hs from g_h[dir][pr] (contiguous 32KB) ----
        {
            const float4* src = reinterpret_cast<const float4*>(&g_h[dir][pr][0][0]);
            float4* dst = reinterpret_cast<float4*>(hs);
            for (int i = tid; i < 2048; i += 256) dst[i] = src[i];
        }

        // ---- prefetch xp gate values (cell role) ----
        bool act = (tid < 128) && (t < Ls[b_cell]);
        float xg0 = 0.f, xg1 = 0.f, xg2 = 0.f, xg3 = 0.f;
        int ob = 0;
        if (act) {
            ob = perm_s[b_cell];
            size_t xb = ((size_t)ob * TT + t) * GG + (size_t)ci * 4 + u_cell;
            xg0 = xp[xb];
            xg1 = xp[xb + 256];
            xg2 = xp[xb + 512];
            xg3 = xp[xb + 768];
        }
        __syncthreads();   // hs ready; pbuf from previous step fully consumed

        // ---- micro-GEMM: whole-warp skip for finished batch groups ----
        if (bg * 4 < A) {
            float acc[4][4];
#pragma unroll
            for (int i = 0; i < 4; i++)
#pragma unroll
                for (int j = 0; j < 4; j++) acc[i][j] = 0.f;
            int kb = ks * 32;
#pragma unroll 8
            for (int k = 0; k < 32; k++) {
                float4 wv = W4[(kb + k) * 4 + rowg];
                float4 hv = H4[(kb + k) * 8 + bg];
                acc[0][0] += wv.x * hv.x; acc[0][1] += wv.x * hv.y;
                acc[0][2] += wv.x * hv.z; acc[0][3] += wv.x * hv.w;
                acc[1][0] += wv.y * hv.x; acc[1][1] += wv.y * hv.y;
                acc[1][2] += wv.y * hv.z; acc[1][3] += wv.y * hv.w;
                acc[2][0] += wv.z * hv.x; acc[2][1] += wv.z * hv.y;
                acc[2][2] += wv.z * hv.z; acc[2][3] += wv.z * hv.w;
                acc[3][0] += wv.w * hv.x; acc[3][1] += wv.w * hv.y;
                acc[3][2] += wv.w * hv.z; acc[3][3] += wv.w * hv.w;
            }
#pragma unroll
            for (int i = 0; i < 4; i++)
#pragma unroll
                for (int j = 0; j < 4; j++)
                    pbuf[(ks * 16 + rowg * 4 + i) * 32 + bg * 4 + j] = acc[i][j];
        }
        __syncthreads();

        // ---- reduce 8 k-slices + cell update ----
        if (act) {
            float g4[4];
#pragma unroll
            for (int q = 0; q < 4; q++) {
                int r = q * 4 + u_cell;
                float v = 0.f;
#pragma unroll
                for (int s2 = 0; s2 < 8; s2++)
                    v += pbuf[(s2 * 16 + r) * 32 + b_cell];
                g4[q] = v;
            }
            g4[0] += xg0; g4[1] += xg1; g4[2] += xg2; g4[3] += xg3;
            float i_ = 1.f / (1.f + __expf(-g4[0]));
            float f_ = 1.f / (1.f + __expf(-g4[1]));
            float o_ = 1.f / (1.f + __expf(-g4[3]));
            c_state = f_ * c_state + i_ * tanhf(g4[2]);
            float hv = o_ * tanhf(c_state);
            int j = ci * 4 + u_cell;
            g_h[dir][pw][j][b_cell] = hv;
            out[((size_t)ob * TT + t) * HH + j] = hv;
        }

        // ---- grid barrier (per direction): flag array, monotone values ----
        __threadfence();
        __syncthreads();
        if (tid == 0) *((volatile int*)&g_flag[dir][ci]) = t + 1;
        if (tid < 64) {
            while (*((volatile int*)&g_flag[dir][tid]) <= t) { }
        }
        __syncthreads();
        __threadfence();
    }
}

// ---------------- kernel 3: logits = log_softmax(concat(out_f, rev(out_b)) @ W_fc^T) ---
__global__ __launch_bounds__(256)
void logits_kernel(const int* __restrict__ seq_len,
                   const float* __restrict__ W_fc)
{
    int bt = blockIdx.x;
    int b = bt / TT, t = bt % TT;
    int L = seq_len[b];
    if (t >= L) return;

    __shared__ float outs[2 * HH];
    __shared__ float dots[CC];
    __shared__ float lse_s;

    int tid = threadIdx.x;  // 256
    outs[tid]       = g_out_f[(size_t)bt * HH + tid];
    outs[HH + tid]  = g_out_b[(size_t)(b * TT + (L - 1 - t)) * HH + tid];
    __syncthreads();

    int warp = tid >> 5, lane = tid & 31;
    for (int cls = warp; cls < CC; cls += 8) {
        float acc = 0.f;
#pragma unroll 4
        for (int e = lane; e < 2 * HH; e += 32)
            acc += outs[e] * W_fc[cls * (2 * HH) + e];
#pragma unroll
        for (int off = 16; off; off >>= 1)
            acc += __shfl_down_sync(0xffffffffu, acc, off);
        if (lane == 0) dots[cls] = acc;
    }
    __syncthreads();

    if (tid == 0) {
        float m = -INFINITY;
        for (int cI = 0; cI < CC; cI++) m = fmaxf(m, dots[cI]);
        float sum = 0.f;
        for (int cI = 0; cI < CC; cI++) sum += expf(dots[cI] - m);
        lse_s = m + logf(sum);
    }
    __syncthreads();

    if (tid < CC) g_logits[(size_t)bt * CC + tid] = dots[tid] - lse_s;
}

// ---------------- kernel 4: CRF gold score + forward algorithm, warp per batch ----------
__global__ __launch_bounds__(32)
void crf_kernel(const int* __restrict__ seq_len, const int* __restrict__ y,
                const float* __restrict__ start_t, const float* __restrict__ end_t,
                const float* __restrict__ trans)
{
    int b = blockIdx.x;
    int lane = threadIdx.x;  // 32

    __shared__ float trans_s[CC * CC];
    __shared__ float alpha_s[CC];
    for (int i = lane; i < CC * CC; i += 32) trans_s[i] = trans[i];
    __syncwarp();

    int L = seq_len[b];
    const float* lg = g_logits + (size_t)b * TT * CC;
    const int* yb = y + b * TT;

    float part = 0.f;
    for (int t = 1 + lane; t < L; t += 32)
        part += trans_s[yb[t - 1] * CC + yb[t]] + lg[t * CC + yb[t]];
#pragma unroll
    for (int off = 16; off; off >>= 1)
        part += __shfl_down_sync(0xffffffffu, part, off);

    float score = 0.f;
    if (lane == 0)
        score = part + start_t[yb[0]] + lg[yb[0]] + end_t[yb[L - 1]];

    int j = lane;
    float alpha = (j < CC) ? (start_t[j] + lg[j]) : -INFINITY;
    for (int t = 1; t < L; t++) {
        if (j < CC) alpha_s[j] = alpha;
        __syncwarp();
        float na = alpha;
        if (j < CC) {
            float m = -INFINITY;
#pragma unroll
            for (int i = 0; i < CC; i++)
                m = fmaxf(m, alpha_s[i] + trans_s[i * CC + j]);
            float sum = 0.f;
#pragma unroll
            for (int i = 0; i < CC; i++)
                sum += expf(alpha_s[i] + trans_s[i * CC + j] - m);
            na = m + logf(sum) + lg[t * CC + j];
        }
        __syncwarp();
        alpha = na;
    }

    if (j < CC) alpha_s[j] = alpha + end_t[j];
    __syncwarp();
    if (lane == 0) {
        float m = -INFINITY;
        for (int i = 0; i < CC; i++) m = fmaxf(m, alpha_s[i]);
        float sum = 0.f;
        for (int i = 0; i < CC; i++) sum += expf(alpha_s[i] - m);
        float logZ = m + logf(sum);
        g_llh[b] = score - logZ;
    }
}

// ---------------- kernel 5: loss = -sum_b llh[b] ----------------
__global__ __launch_bounds__(32)
void finalize_kernel(float* __restrict__ out)
{
    int lane = threadIdx.x;
    float v = g_llh[lane];
#pragma unroll
    for (int off = 16; off; off >>= 1)
        v += __shfl_down_sync(0xffffffffu, v, off);
    if (lane == 0) out[0] = -v;
}

// ---------------- launch ----------------
extern "C" void kernel_launch(void* const* d_in, const int* in_sizes, int n_in,
                              void* d_out, int out_size)
{
    (void)in_sizes; (void)n_in; (void)out_size;
    const int*   x       = (const int*)  d_in[0];
    const int*   seq_len = (const int*)  d_in[1];
    const int*   y       = (const int*)  d_in[2];
    // d_in[3] = mask (derived from seq_len instead)
    const float* emb     = (const float*)d_in[4];
    const float* Wih_f   = (const float*)d_in[5];
    const float* Whh_f   = (const float*)d_in[6];
    const float* b_f     = (const float*)d_in[7];
    const float* Wih_b   = (const float*)d_in[8];
    const float* Whh_b   = (const float*)d_in[9];
    const float* b_b     = (const float*)d_in[10];
    const float* W_fc    = (const float*)d_in[11];
    const float* start_t = (const float*)d_in[12];
    const float* end_t   = (const float*)d_in[13];
    const float* trans   = (const float*)d_in[14];
    float* out = (float*)d_out;

    // scan dynamic SMEM: Ws 16KB + hs 32KB + pbuf 16KB = 64KB
    const int scan_smem = (256 * 16 + 256 * 32 + 8 * 16 * 32) * (int)sizeof(float);
    static int smem_set = 0;
    if (!smem_set) {
        cudaFuncSetAttribute(lstm_scan2,
                             cudaFuncAttributeMaxDynamicSharedMemorySize, scan_smem);
        smem_set = 1;
    }

    setup_kernel<<<1, 256>>>(seq_len);

    dim3 ggrid(GG / 128, MM / 128);
    gemm_xp<<<ggrid, 256>>>(x, seq_len, emb, Wih_f, b_f, 0);
    gemm_xp<<<ggrid, 256>>>(x, seq_len, emb, Wih_b, b_b, 1);

    lstm_scan2<<<128, 256, scan_smem>>>(Whh_f, Whh_b);

    logits_kernel<<<MM, 256>>>(seq_len, W_fc);

    crf_kernel<<<BB, 32>>>(seq_len, y, start_t, end_t, trans);

    finalize_kernel<<<1, 32>>>(out);
}

// round 7
// speedup vs baseline: 1.2803x; 1.2803x over previous
#include <cuda_runtime.h>
#include <math.h>
#include <stdint.h>

// Problem constants
#define BB 32
#define TT 512
#define EE 256
#define HH 256
#define GG 1024          // 4*H
#define CC 20
#define MM (BB * TT)     // 16384

// ---------------- device scratch (allocation-free rule: static __device__) --------------
__device__ float g_xp_f[(size_t)MM * GG];   // 64 MB
__device__ float g_xp_b[(size_t)MM * GG];   // 64 MB
__device__ float g_out_f[(size_t)MM * HH];  // 16 MB
__device__ float g_out_b[(size_t)MM * HH];  // 16 MB
__device__ float g_logits[(size_t)MM * CC];
__device__ float g_llh[BB];

// persistent-scan state
__device__ float    g_h[2][2][HH][BB];      // [dir][parity][j][b_sorted]
__device__ unsigned g_bar[2];               // per-direction arrival counter
__device__ int      g_perm[BB];             // sorted(batch) -> original batch
__device__ int      g_Lsorted[BB];          // lengths, descending
__device__ int      g_Lmax;

// GEMM compaction
__device__ int   g_rows[MM];                // packed (b<<16)|t for t < seq_len[b]
__device__ int   g_nrows;

// ---------------- kernel 0: setup ----------------
__global__ __launch_bounds__(256)
void setup_kernel(const int* __restrict__ seq_len)
{
    __shared__ int off_s[BB + 1];
    int tid = threadIdx.x;

    // zero h buffers (2*2*256*32 = 32768 floats)
    for (int i = tid; i < 2 * 2 * HH * BB; i += 256)
        (&g_h[0][0][0][0])[i] = 0.f;

    if (tid == 0) {
        int L[BB], p[BB];
        for (int i = 0; i < BB; i++) { L[i] = seq_len[i]; p[i] = i; }
        // stable insertion sort, descending by L
        for (int i = 1; i < BB; i++) {
            int kl = L[i], kp = p[i];
            int j = i - 1;
            while (j >= 0 && L[j] < kl) { L[j + 1] = L[j]; p[j + 1] = p[j]; j--; }
            L[j + 1] = kl; p[j + 1] = kp;
        }
        for (int i = 0; i < BB; i++) { g_perm[i] = p[i]; g_Lsorted[i] = L[i]; }
        g_Lmax = L[0];
        g_bar[0] = 0u;
        g_bar[1] = 0u;
        // prefix offsets in ORIGINAL batch order for row compaction
        int off = 0;
        for (int b = 0; b < BB; b++) { off_s[b] = off; off += seq_len[b]; }
        off_s[BB] = off;
        g_nrows = off;
    }
    __syncthreads();

    // fill compacted row list: thread group (b, r) writes rows t = r, r+8, ...
    int b = tid >> 3, r = tid & 7;
    int off = off_s[b];
    int L = off_s[b + 1] - off;
    for (int t = r; t < L; t += 8)
        g_rows[off + t] = (b << 16) | t;
}

// ---------------- kernel 1: xp = gather(emb, x[, reversed]) @ Wih^T + bias -------------
// Compacted M (only t < seq_len rows). Tile 128x128, BK=8, 256 threads, 8x8 per thread.
__global__ __launch_bounds__(256)
void gemm_xp(const int* __restrict__ x, const int* __restrict__ seq_len,
             const float* __restrict__ emb, const float* __restrict__ Wih,
             const float* __restrict__ bias, int rev)
{
    const int BM = 128, BN = 128, BK = 8;
    __shared__ float As[BK][BM];
    __shared__ float Bs[BK][BN];
    __shared__ int tok[BM];
    __shared__ int orow[BM];

    int nrows = g_nrows;
    int m0 = blockIdx.y * BM;
    if (m0 >= nrows) return;

    float* __restrict__ xp = rev ? g_xp_b : g_xp_f;

    int tid = threadIdx.x;                 // 256
    int n0 = blockIdx.x * BN;

    if (tid < BM) {
        int m = m0 + tid;
        if (m < nrows) {
            int pk = g_rows[m];
            int b = pk >> 16, t = pk & 0xFFFF;
            int tp = rev ? (seq_len[b] - 1 - t) : t;   // t < L by construction
            tok[tid]  = x[b * TT + tp];
            orow[tid] = b * TT + t;
        } else {
            tok[tid] = 0;
            orow[tid] = -1;
        }
    }
    __syncthreads();

    int tx = tid & 15, ty = tid >> 4;
    int am = tid >> 1, ak = (tid & 1) * 4;
    int bn = tid >> 1, bk = (tid & 1) * 4;

    float acc[8][8];
#pragma unroll
    for (int i = 0; i < 8; i++)
#pragma unroll
        for (int j = 0; j < 8; j++) acc[i][j] = 0.f;

    for (int k0 = 0; k0 < EE; k0 += BK) {
        float4 av = *reinterpret_cast<const float4*>(
            &emb[(size_t)tok[am] * EE + k0 + ak]);
        float4 bv = *reinterpret_cast<const float4*>(
            &Wih[(size_t)(n0 + bn) * EE + k0 + bk]);
        __syncthreads();   // previous tile fully consumed
        As[ak + 0][am] = av.x; As[ak + 1][am] = av.y;
        As[ak + 2][am] = av.z; As[ak + 3][am] = av.w;
        Bs[bk + 0][bn] = bv.x; Bs[bk + 1][bn] = bv.y;
        Bs[bk + 2][bn] = bv.z; Bs[bk + 3][bn] = bv.w;
        __syncthreads();

#pragma unroll
        for (int kk = 0; kk < BK; kk++) {
            float a[8], b[8];
            *reinterpret_cast<float4*>(&a[0]) =
                *reinterpret_cast<const float4*>(&As[kk][ty * 8]);
            *reinterpret_cast<float4*>(&a[4]) =
                *reinterpret_cast<const float4*>(&As[kk][ty * 8 + 4]);
            *reinterpret_cast<float4*>(&b[0]) =
                *reinterpret_cast<const float4*>(&Bs[kk][tx * 8]);
            *reinterpret_cast<float4*>(&b[4]) =
                *reinterpret_cast<const float4*>(&Bs[kk][tx * 8 + 4]);
#pragma unroll
            for (int i = 0; i < 8; i++)
#pragma unroll
                for (int j = 0; j < 8; j++) acc[i][j] += a[i] * b[j];
        }
    }

    float bj[8];
#pragma unroll
    for (int j = 0; j < 8; j++) bj[j] = bias[n0 + tx * 8 + j];
#pragma unroll
    for (int i = 0; i < 8; i++) {
        int om = orow[ty * 8 + i];
        if (om >= 0) {
            size_t row = (size_t)om * GG + n0 + tx * 8;
            float4 v0, v1;
            v0.x = acc[i][0] + bj[0]; v0.y = acc[i][1] + bj[1];
            v0.z = acc[i][2] + bj[2]; v0.w = acc[i][3] + bj[3];
            v1.x = acc[i][4] + bj[4]; v1.y = acc[i][5] + bj[5];
            v1.z = acc[i][6] + bj[6]; v1.w = acc[i][7] + bj[7];
            *reinterpret_cast<float4*>(&xp[row]) = v0;
            *reinterpret_cast<float4*>(&xp[row + 4]) = v1;
        }
    }
}

// ---------------- kernel 2: persistent batched LSTM scan --------------------------------
// 64 CTAs: dir = bid>>5, ci = bid&31. CTA owns hidden units [ci*8, ci*8+8)
// (32 gate rows, 32KB of Whh in SMEM for the whole scan).
// Warp w owns batches [4w, 4w+4): lane = u*4 + bl accumulates the 4 gate values of
// (hidden unit u, batch 4w+bl) over ALL 256 k in registers -> no partial buffer,
// no reduce, warp-uniform early exit for finished batches.
// h exchange via g_h double buffer + atomic-counter grid barrier (per direction).
__global__ __launch_bounds__(256)
void lstm_scan3(const float* __restrict__ Whh_f, const float* __restrict__ Whh_b)
{
    extern __shared__ float sm[];
    float* Ws = sm;              // [256][32]  Ws[k*32 + u*4 + q]
    float* hs = sm + 256 * 32;   // [256][32]  hs[k*32 + b]
    __shared__ int perm_s[BB];
    __shared__ int Ls[BB];

    int dir = blockIdx.x >> 5;
    int ci  = blockIdx.x & 31;
    int tid = threadIdx.x;

    const float* __restrict__ xp  = dir ? g_xp_b : g_xp_f;
    const float* __restrict__ Whh = dir ? Whh_b : Whh_f;
    float* __restrict__ out       = dir ? g_out_b : g_out_f;

    if (tid < BB) { perm_s[tid] = g_perm[tid]; Ls[tid] = g_Lsorted[tid]; }
    int Lmax = g_Lmax;

    // ---- fill weight slice into SMEM: Ws[k][u*4+q], grow = q*256 + ci*8 + u ----
    for (int i = tid; i < 32 * 64; i += 256) {
        int lrow = i & 31, k4 = i >> 5;
        int u = lrow >> 2, q = lrow & 3;
        int grow = q * 256 + ci * 8 + u;
        float4 w = *reinterpret_cast<const float4*>(&Whh[(size_t)grow * 256 + k4 * 4]);
        Ws[(k4 * 4 + 0) * 32 + lrow] = w.x;
        Ws[(k4 * 4 + 1) * 32 + lrow] = w.y;
        Ws[(k4 * 4 + 2) * 32 + lrow] = w.z;
        Ws[(k4 * 4 + 3) * 32 + lrow] = w.w;
    }
    __syncthreads();

    int wid  = tid >> 5;
    int lane = tid & 31;
    int u  = lane >> 2;          // hidden unit within CTA slice
    int bl = lane & 3;
    int b  = wid * 4 + bl;       // sorted batch index
    int j  = ci * 8 + u;         // global hidden unit

    const float4* W4 = reinterpret_cast<const float4*>(Ws);   // [k][8] float4 by u

    float c_state = 0.f;
    int A = BB;

    for (int t = 0; t < Lmax; t++) {
        while (A > 0 && Ls[A - 1] <= t) A--;
        int pw = t & 1, pr = pw ^ 1;

        // ---- fill hs from g_h[dir][pr] (contiguous 32KB) ----
        {
            const float4* src = reinterpret_cast<const float4*>(&g_h[dir][pr][0][0]);
            float4* dst = reinterpret_cast<float4*>(hs);
            for (int i = tid; i < 2048; i += 256) dst[i] = src[i];
        }

        // ---- prefetch this lane's xp gate values ----
        bool act = (t < Ls[b]);
        int ob = 0;
        float xg0 = 0.f, xg1 = 0.f, xg2 = 0.f, xg3 = 0.f;
        if (act) {
            ob = perm_s[b];
            size_t xb = ((size_t)ob * TT + t) * GG + (size_t)ci * 8 + u;
            xg0 = xp[xb];
            xg1 = xp[xb + 256];
            xg2 = xp[xb + 512];
            xg3 = xp[xb + 768];
        }
        __syncthreads();   // hs ready; previous-step hs reads all retired (barrier below)

        // ---- register-resident matvec over all 256 k; whole-warp skip ----
        if (wid * 4 < A) {
            float a0 = 0.f, a1 = 0.f, a2 = 0.f, a3 = 0.f;
#pragma unroll 8
            for (int k = 0; k < 256; k++) {
                float4 wv = W4[k * 8 + u];
                float hv = hs[k * 32 + b];
                a0 += wv.x * hv;
                a1 += wv.y * hv;
                a2 += wv.z * hv;
                a3 += wv.w * hv;
            }
            if (act) {
                float gi = a0 + xg0;
                float gf = a1 + xg1;
                float gg = a2 + xg2;
                float go = a3 + xg3;
                float i_ = 1.f / (1.f + __expf(-gi));
                float f_ = 1.f / (1.f + __expf(-gf));
                float o_ = 1.f / (1.f + __expf(-go));
                c_state = f_ * c_state + i_ * tanhf(gg);
                float hv = o_ * tanhf(c_state);
                g_h[dir][pw][j][b] = hv;
                out[((size_t)ob * TT + t) * HH + j] = hv;
            }
        }

        // ---- grid barrier (per direction), monotone counter ----
        __threadfence();
        __syncthreads();
        if (tid == 0) {
            atomicAdd(&g_bar[dir], 1u);
            unsigned tgt = 32u * (unsigned)(t + 1);
            while (*((volatile unsigned*)&g_bar[dir]) < tgt) { }
        }
        __syncthreads();
        __threadfence();
    }
}

// ---------------- kernel 3: logits = log_softmax(concat(out_f, rev(out_b)) @ W_fc^T) ---
__global__ __launch_bounds__(256)
void logits_kernel(const int* __restrict__ seq_len,
                   const float* __restrict__ W_fc)
{
    int bt = blockIdx.x;
    int b = bt / TT, t = bt % TT;
    int L = seq_len[b];
    if (t >= L) return;

    __shared__ float outs[2 * HH];
    __shared__ float dots[CC];
    __shared__ float lse_s;

    int tid = threadIdx.x;  // 256
    outs[tid]       = g_out_f[(size_t)bt * HH + tid];
    outs[HH + tid]  = g_out_b[(size_t)(b * TT + (L - 1 - t)) * HH + tid];
    __syncthreads();

    int warp = tid >> 5, lane = tid & 31;
    for (int cls = warp; cls < CC; cls += 8) {
        float acc = 0.f;
#pragma unroll 4
        for (int e = lane; e < 2 * HH; e += 32)
            acc += outs[e] * W_fc[cls * (2 * HH) + e];
#pragma unroll
        for (int off = 16; off; off >>= 1)
            acc += __shfl_down_sync(0xffffffffu, acc, off);
        if (lane == 0) dots[cls] = acc;
    }
    __syncthreads();

    if (tid == 0) {
        float m = -INFINITY;
        for (int cI = 0; cI < CC; cI++) m = fmaxf(m, dots[cI]);
        float sum = 0.f;
        for (int cI = 0; cI < CC; cI++) sum += expf(dots[cI] - m);
        lse_s = m + logf(sum);
    }
    __syncthreads();

    if (tid < CC) g_logits[(size_t)bt * CC + tid] = dots[tid] - lse_s;
}

// ---------------- kernel 4: CRF gold score + forward algorithm, warp per batch ----------
__global__ __launch_bounds__(32)
void crf_kernel(const int* __restrict__ seq_len, const int* __restrict__ y,
                const float* __restrict__ start_t, const float* __restrict__ end_t,
                const float* __restrict__ trans)
{
    int b = blockIdx.x;
    int lane = threadIdx.x;  // 32

    __shared__ float trans_s[CC * CC];
    __shared__ float alpha_s[CC];
    for (int i = lane; i < CC * CC; i += 32) trans_s[i] = trans[i];
    __syncwarp();

    int L = seq_len[b];
    const float* lg = g_logits + (size_t)b * TT * CC;
    const int* yb = y + b * TT;

    float part = 0.f;
    for (int t = 1 + lane; t < L; t += 32)
        part += trans_s[yb[t - 1] * CC + yb[t]] + lg[t * CC + yb[t]];
#pragma unroll
    for (int off = 16; off; off >>= 1)
        part += __shfl_down_sync(0xffffffffu, part, off);

    float score = 0.f;
    if (lane == 0)
        score = part + start_t[yb[0]] + lg[yb[0]] + end_t[yb[L - 1]];

    int j = lane;
    float alpha = (j < CC) ? (start_t[j] + lg[j]) : -INFINITY;
    for (int t = 1; t < L; t++) {
        if (j < CC) alpha_s[j] = alpha;
        __syncwarp();
        float na = alpha;
        if (j < CC) {
            float m = -INFINITY;
#pragma unroll
            for (int i = 0; i < CC; i++)
                m = fmaxf(m, alpha_s[i] + trans_s[i * CC + j]);
            float sum = 0.f;
#pragma unroll
            for (int i = 0; i < CC; i++)
                sum += expf(alpha_s[i] + trans_s[i * CC + j] - m);
            na = m + logf(sum) + lg[t * CC + j];
        }
        __syncwarp();
        alpha = na;
    }

    if (j < CC) alpha_s[j] = alpha + end_t[j];
    __syncwarp();
    if (lane == 0) {
        float m = -INFINITY;
        for (int i = 0; i < CC; i++) m = fmaxf(m, alpha_s[i]);
        float sum = 0.f;
        for (int i = 0; i < CC; i++) sum += expf(alpha_s[i] - m);
        float logZ = m + logf(sum);
        g_llh[b] = score - logZ;
    }
}

// ---------------- kernel 5: loss = -sum_b llh[b] ----------------
__global__ __launch_bounds__(32)
void finalize_kernel(float* __restrict__ out)
{
    int lane = threadIdx.x;
    float v = g_llh[lane];
#pragma unroll
    for (int off = 16; off; off >>= 1)
        v += __shfl_down_sync(0xffffffffu, v, off);
    if (lane == 0) out[0] = -v;
}

// ---------------- launch ----------------
extern "C" void kernel_launch(void* const* d_in, const int* in_sizes, int n_in,
                              void* d_out, int out_size)
{
    (void)in_sizes; (void)n_in; (void)out_size;
    const int*   x       = (const int*)  d_in[0];
    const int*   seq_len = (const int*)  d_in[1];
    const int*   y       = (const int*)  d_in[2];
    // d_in[3] = mask (derived from seq_len instead)
    const float* emb     = (const float*)d_in[4];
    const float* Wih_f   = (const float*)d_in[5];
    const float* Whh_f   = (const float*)d_in[6];
    const float* b_f     = (const float*)d_in[7];
    const float* Wih_b   = (const float*)d_in[8];
    const float* Whh_b   = (const float*)d_in[9];
    const float* b_b     = (const float*)d_in[10];
    const float* W_fc    = (const float*)d_in[11];
    const float* start_t = (const float*)d_in[12];
    const float* end_t   = (const float*)d_in[13];
    const float* trans   = (const float*)d_in[14];
    float* out = (float*)d_out;

    // scan dynamic SMEM: Ws 32KB + hs 32KB = 64KB
    const int scan_smem = (2 * 256 * 32) * (int)sizeof(float);
    static int smem_set = 0;
    if (!smem_set) {
        cudaFuncSetAttribute(lstm_scan3,
                             cudaFuncAttributeMaxDynamicSharedMemorySize, scan_smem);
        smem_set = 1;
    }

    setup_kernel<<<1, 256>>>(seq_len);

    dim3 ggrid(GG / 128, MM / 128);
    gemm_xp<<<ggrid, 256>>>(x, seq_len, emb, Wih_f, b_f, 0);
    gemm_xp<<<ggrid, 256>>>(x, seq_len, emb, Wih_b, b_b, 1);

    lstm_scan3<<<64, 256, scan_smem>>>(Whh_f, Whh_b);

    logits_kernel<<<MM, 256>>>(seq_len, W_fc);

    crf_kernel<<<BB, 32>>>(seq_len, y, start_t, end_t, trans);

    finalize_kernel<<<1, 32>>>(out);
}

// round 8
// speedup vs baseline: 1.6381x; 1.2794x over previous
#include <cuda_runtime.h>
#include <math.h>
#include <stdint.h>

// Problem constants
#define BB 32
#define TT 512
#define EE 256
#define HH 256
#define GG 1024          // 4*H
#define CC 20
#define MM (BB * TT)     // 16384

// ---------------- device scratch (allocation-free rule: static __device__) --------------
__device__ float g_xp_f[(size_t)MM * GG];   // 64 MB
__device__ float g_xp_b[(size_t)MM * GG];   // 64 MB
__device__ float g_out_f[(size_t)MM * HH];  // 16 MB
__device__ float g_out_b[(size_t)MM * HH];  // 16 MB
__device__ float g_logits[(size_t)MM * CC];
__device__ float g_llh[BB];

// persistent-scan state
__device__ float    g_h[2][2][HH][BB];      // [dir][parity][j][b_sorted]
__device__ unsigned g_bar[2];               // per-direction arrival counter
__device__ int      g_perm[BB];             // sorted(batch) -> original batch
__device__ int      g_Lsorted[BB];          // lengths, descending
__device__ int      g_Lmax;

// GEMM compaction
__device__ int   g_rows[MM];                // packed (b<<16)|t for t < seq_len[b]
__device__ int   g_nrows;

// ---------------- kernel 0: setup ----------------
__global__ __launch_bounds__(256)
void setup_kernel(const int* __restrict__ seq_len)
{
    __shared__ int off_s[BB + 1];
    int tid = threadIdx.x;

    // zero h buffers (2*2*256*32 = 32768 floats)
    for (int i = tid; i < 2 * 2 * HH * BB; i += 256)
        (&g_h[0][0][0][0])[i] = 0.f;

    if (tid == 0) {
        int L[BB], p[BB];
        for (int i = 0; i < BB; i++) { L[i] = seq_len[i]; p[i] = i; }
        // stable insertion sort, descending by L
        for (int i = 1; i < BB; i++) {
            int kl = L[i], kp = p[i];
            int j = i - 1;
            while (j >= 0 && L[j] < kl) { L[j + 1] = L[j]; p[j + 1] = p[j]; j--; }
            L[j + 1] = kl; p[j + 1] = kp;
        }
        for (int i = 0; i < BB; i++) { g_perm[i] = p[i]; g_Lsorted[i] = L[i]; }
        g_Lmax = L[0];
        g_bar[0] = 0u;
        g_bar[1] = 0u;
        // prefix offsets in ORIGINAL batch order for row compaction
        int off = 0;
        for (int b = 0; b < BB; b++) { off_s[b] = off; off += seq_len[b]; }
        off_s[BB] = off;
        g_nrows = off;
    }
    __syncthreads();

    // fill compacted row list: thread group (b, r) writes rows t = r, r+8, ...
    int b = tid >> 3, r = tid & 7;
    int off = off_s[b];
    int L = off_s[b + 1] - off;
    for (int t = r; t < L; t += 8)
        g_rows[off + t] = (b << 16) | t;
}

// ---------------- kernel 1: xp = gather(emb, x[, reversed]) @ Wih^T + bias -------------
// Compacted M (only t < seq_len rows). Tile 128x128, BK=8, 256 threads, 8x8 per thread.
__global__ __launch_bounds__(256)
void gemm_xp(const int* __restrict__ x, const int* __restrict__ seq_len,
             const float* __restrict__ emb, const float* __restrict__ Wih,
             const float* __restrict__ bias, int rev)
{
    const int BM = 128, BN = 128, BK = 8;
    __shared__ float As[BK][BM];
    __shared__ float Bs[BK][BN];
    __shared__ int tok[BM];
    __shared__ int orow[BM];

    int nrows = g_nrows;
    int m0 = blockIdx.y * BM;
    if (m0 >= nrows) return;

    float* __restrict__ xp = rev ? g_xp_b : g_xp_f;

    int tid = threadIdx.x;                 // 256
    int n0 = blockIdx.x * BN;

    if (tid < BM) {
        int m = m0 + tid;
        if (m < nrows) {
            int pk = g_rows[m];
            int b = pk >> 16, t = pk & 0xFFFF;
            int tp = rev ? (seq_len[b] - 1 - t) : t;   // t < L by construction
            tok[tid]  = x[b * TT + tp];
            orow[tid] = b * TT + t;
        } else {
            tok[tid] = 0;
            orow[tid] = -1;
        }
    }
    __syncthreads();

    int tx = tid & 15, ty = tid >> 4;
    int am = tid >> 1, ak = (tid & 1) * 4;
    int bn = tid >> 1, bk = (tid & 1) * 4;

    float acc[8][8];
#pragma unroll
    for (int i = 0; i < 8; i++)
#pragma unroll
        for (int j = 0; j < 8; j++) acc[i][j] = 0.f;

    for (int k0 = 0; k0 < EE; k0 += BK) {
        float4 av = *reinterpret_cast<const float4*>(
            &emb[(size_t)tok[am] * EE + k0 + ak]);
        float4 bv = *reinterpret_cast<const float4*>(
            &Wih[(size_t)(n0 + bn) * EE + k0 + bk]);
        __syncthreads();   // previous tile fully consumed
        As[ak + 0][am] = av.x; As[ak + 1][am] = av.y;
        As[ak + 2][am] = av.z; As[ak + 3][am] = av.w;
        Bs[bk + 0][bn] = bv.x; Bs[bk + 1][bn] = bv.y;
        Bs[bk + 2][bn] = bv.z; Bs[bk + 3][bn] = bv.w;
        __syncthreads();

#pragma unroll
        for (int kk = 0; kk < BK; kk++) {
            float a[8], b[8];
            *reinterpret_cast<float4*>(&a[0]) =
                *reinterpret_cast<const float4*>(&As[kk][ty * 8]);
            *reinterpret_cast<float4*>(&a[4]) =
                *reinterpret_cast<const float4*>(&As[kk][ty * 8 + 4]);
            *reinterpret_cast<float4*>(&b[0]) =
                *reinterpret_cast<const float4*>(&Bs[kk][tx * 8]);
            *reinterpret_cast<float4*>(&b[4]) =
                *reinterpret_cast<const float4*>(&Bs[kk][tx * 8 + 4]);
#pragma unroll
            for (int i = 0; i < 8; i++)
#pragma unroll
                for (int j = 0; j < 8; j++) acc[i][j] += a[i] * b[j];
        }
    }

    float bj[8];
#pragma unroll
    for (int j = 0; j < 8; j++) bj[j] = bias[n0 + tx * 8 + j];
#pragma unroll
    for (int i = 0; i < 8; i++) {
        int om = orow[ty * 8 + i];
        if (om >= 0) {
            size_t row = (size_t)om * GG + n0 + tx * 8;
            float4 v0, v1;
            v0.x = acc[i][0] + bj[0]; v0.y = acc[i][1] + bj[1];
            v0.z = acc[i][2] + bj[2]; v0.w = acc[i][3] + bj[3];
            v1.x = acc[i][4] + bj[4]; v1.y = acc[i][5] + bj[5];
            v1.z = acc[i][6] + bj[6]; v1.w = acc[i][7] + bj[7];
            *reinterpret_cast<float4*>(&xp[row]) = v0;
            *reinterpret_cast<float4*>(&xp[row + 4]) = v1;
        }
    }
}

// ---------------- kernel 2: persistent batched LSTM scan (R5-proven layout) ------------
// 64 CTAs total: dir = bid>>5, ci = bid&31. CTA owns hidden units j in [ci*8, ci*8+8)
// (32 gate rows, 32KB of Whh in SMEM, k-major, for the entire scan).
// Per step: tiny GEMM (32 rows x A batches x 256 k) from SMEM (4x4 register micro-tile,
// 4 k-slices reduced via pbuf), cell update, h exchange through g_h (double-buffered)
// + monotone atomic-counter grid barrier per direction.
__global__ __launch_bounds__(256)
void lstm_scan2(const float* __restrict__ Whh_f, const float* __restrict__ Whh_b)
{
    extern __shared__ float sm[];
    float* Ws   = sm;                    // [256][32]  Ws[k*32 + lrow]
    float* hs   = sm + 256 * 32;         // [256][32]  hs[k*32 + b]
    float* pbuf = sm + 2 * 256 * 32;     // [4][32][32] pbuf[(s*32+r)*32 + b]
    __shared__ int perm_s[BB];
    __shared__ int Ls[BB];

    int dir = blockIdx.x >> 5;
    int ci  = blockIdx.x & 31;
    int tid = threadIdx.x;

    const float* __restrict__ xp  = dir ? g_xp_b : g_xp_f;
    const float* __restrict__ Whh = dir ? Whh_b : Whh_f;
    float* __restrict__ out       = dir ? g_out_b : g_out_f;

    if (tid < BB) { perm_s[tid] = g_perm[tid]; Ls[tid] = g_Lsorted[tid]; }
    int Lmax = g_Lmax;

    // ---- fill weight slice into SMEM, k-major: Ws[k][lrow], lrow = q*8+u ----
    for (int i = tid; i < 32 * 64; i += 256) {
        int lrow = i & 31, k4 = i >> 5;
        int q = lrow >> 3, u = lrow & 7;
        int grow = q * 256 + ci * 8 + u;
        float4 w = *reinterpret_cast<const float4*>(&Whh[(size_t)grow * 256 + k4 * 4]);
        Ws[(k4 * 4 + 0) * 32 + lrow] = w.x;
        Ws[(k4 * 4 + 1) * 32 + lrow] = w.y;
        Ws[(k4 * 4 + 2) * 32 + lrow] = w.z;
        Ws[(k4 * 4 + 3) * 32 + lrow] = w.w;
    }
    __syncthreads();

    // GEMM roles: k-slice s (64 k each), 8 row-groups x 8 batch-groups, 4x4 micro-tile
    int s    = tid >> 6;
    int s64  = tid & 63;
    int rowg = s64 & 7;
    int bg   = s64 >> 3;
    // cell roles: tid = b_cell*8 + u_cell
    int b_cell = tid >> 3;
    int u_cell = tid & 3 + 0;   // placeholder, fixed below
    u_cell = tid & 7;

    float c_state = 0.f;
    int A = BB;

    const float4* W4 = reinterpret_cast<const float4*>(Ws);  // [k][8] float4
    const float4* H4 = reinterpret_cast<const float4*>(hs);

    for (int t = 0; t < Lmax; t++) {
        while (A > 0 && Ls[A - 1] <= t) A--;
        int pw = t & 1, pr = pw ^ 1;
        int nb4 = (A + 3) >> 2;   // active float4 batch-groups

        // ---- fill hs from g_h[dir][pr], active columns only ----
        {
            const float4* src = reinterpret_cast<const float4*>(&g_h[dir][pr][0][0]);
            float4* dst = reinterpret_cast<float4*>(hs);
            for (int i = tid; i < 2048; i += 256)
                if ((i & 7) < nb4) dst[i] = src[i];
        }

        // ---- prefetch this thread's xp gate values (cell role) ----
        int Lb = Ls[b_cell];
        bool act = (t < Lb);
        int ob = perm_s[b_cell];
        float xg0 = 0.f, xg1 = 0.f, xg2 = 0.f, xg3 = 0.f;
        if (act) {
            size_t xbase = ((size_t)ob * TT + t) * GG + (size_t)ci * 8 + u_cell;
            xg0 = xp[xbase];
            xg1 = xp[xbase + 256];
            xg2 = xp[xbase + 512];
            xg3 = xp[xbase + 768];
        }
        __syncthreads();   // hs ready; pbuf from previous step fully consumed

        // ---- micro-GEMM: gates[row][b] partial over k-slice s ----
        float acc[4][4];
#pragma unroll
        for (int i = 0; i < 4; i++)
#pragma unroll
            for (int j = 0; j < 4; j++) acc[i][j] = 0.f;

        if (bg * 4 < A) {
            int kbase = s * 64;
#pragma unroll 8
            for (int k = 0; k < 64; k++) {
                float4 wv = W4[(kbase + k) * 8 + rowg];
                float4 hv = H4[(kbase + k) * 8 + bg];
                acc[0][0] += wv.x * hv.x; acc[0][1] += wv.x * hv.y;
                acc[0][2] += wv.x * hv.z; acc[0][3] += wv.x * hv.w;
                acc[1][0] += wv.y * hv.x; acc[1][1] += wv.y * hv.y;
                acc[1][2] += wv.y * hv.z; acc[1][3] += wv.y * hv.w;
                acc[2][0] += wv.z * hv.x; acc[2][1] += wv.z * hv.y;
                acc[2][2] += wv.z * hv.z; acc[2][3] += wv.z * hv.w;
                acc[3][0] += wv.w * hv.x; acc[3][1] += wv.w * hv.y;
                acc[3][2] += wv.w * hv.z; acc[3][3] += wv.w * hv.w;
            }
        }
#pragma unroll
        for (int i = 0; i < 4; i++)
#pragma unroll
            for (int j = 0; j < 4; j++)
                pbuf[(s * 32 + rowg * 4 + i) * 32 + bg * 4 + j] = acc[i][j];
        __syncthreads();

        // ---- reduce 4 k-slices + cell update + write h/out ----
        if (act) {
            float g4[4];
#pragma unroll
            for (int q = 0; q < 4; q++) {
                int r = q * 8 + u_cell;
                float v = 0.f;
#pragma unroll
                for (int s2 = 0; s2 < 4; s2++)
                    v += pbuf[(s2 * 32 + r) * 32 + b_cell];
                g4[q] = v;
            }
            g4[0] += xg0; g4[1] += xg1; g4[2] += xg2; g4[3] += xg3;
            float i_ = 1.f / (1.f + __expf(-g4[0]));
            float f_ = 1.f / (1.f + __expf(-g4[1]));
            float o_ = 1.f / (1.f + __expf(-g4[3]));
            c_state = f_ * c_state + i_ * tanhf(g4[2]);
            float hv = o_ * tanhf(c_state);
            int j = ci * 8 + u_cell;
            g_h[dir][pw][j][b_cell] = hv;
            out[((size_t)ob * TT + t) * HH + j] = hv;
        }

        // ---- grid barrier (per direction), monotone counter ----
        __threadfence();
        __syncthreads();
        if (tid == 0) {
            atomicAdd(&g_bar[dir], 1u);
            unsigned tgt = 32u * (unsigned)(t + 1);
            while (*((volatile unsigned*)&g_bar[dir]) < tgt) { }
        }
        __syncthreads();
        __threadfence();
    }
}

// ---------------- kernel 3: logits = log_softmax(concat(out_f, rev(out_b)) @ W_fc^T) ---
__global__ __launch_bounds__(256)
void logits_kernel(const int* __restrict__ seq_len,
                   const float* __restrict__ W_fc)
{
    int bt = blockIdx.x;
    int b = bt / TT, t = bt % TT;
    int L = seq_len[b];
    if (t >= L) return;

    __shared__ float outs[2 * HH];
    __shared__ float dots[CC];
    __shared__ float lse_s;

    int tid = threadIdx.x;  // 256
    outs[tid]       = g_out_f[(size_t)bt * HH + tid];
    outs[HH + tid]  = g_out_b[(size_t)(b * TT + (L - 1 - t)) * HH + tid];
    __syncthreads();

    int warp = tid >> 5, lane = tid & 31;
    for (int cls = warp; cls < CC; cls += 8) {
        float acc = 0.f;
#pragma unroll 4
        for (int e = lane; e < 2 * HH; e += 32)
            acc += outs[e] * W_fc[cls * (2 * HH) + e];
#pragma unroll
        for (int off = 16; off; off >>= 1)
            acc += __shfl_down_sync(0xffffffffu, acc, off);
        if (lane == 0) dots[cls] = acc;
    }
    __syncthreads();

    if (tid == 0) {
        float m = -INFINITY;
        for (int cI = 0; cI < CC; cI++) m = fmaxf(m, dots[cI]);
        float sum = 0.f;
        for (int cI = 0; cI < CC; cI++) sum += expf(dots[cI] - m);
        lse_s = m + logf(sum);
    }
    __syncthreads();

    if (tid < CC) g_logits[(size_t)bt * CC + tid] = dots[tid] - lse_s;
}

// ---------------- kernel 4: CRF gold score + forward algorithm, warp per batch ----------
__global__ __launch_bounds__(32)
void crf_kernel(const int* __restrict__ seq_len, const int* __restrict__ y,
                const float* __restrict__ start_t, const float* __restrict__ end_t,
                const float* __restrict__ trans)
{
    int b = blockIdx.x;
    int lane = threadIdx.x;  // 32

    __shared__ float trans_s[CC * CC];
    __shared__ float alpha_s[CC];
    for (int i = lane; i < CC * CC; i += 32) trans_s[i] = trans[i];
    __syncwarp();

    int L = seq_len[b];
    const float* lg = g_logits + (size_t)b * TT * CC;
    const int* yb = y + b * TT;

    float part = 0.f;
    for (int t = 1 + lane; t < L; t += 32)
        part += trans_s[yb[t - 1] * CC + yb[t]] + lg[t * CC + yb[t]];
#pragma unroll
    for (int off = 16; off; off >>= 1)
        part += __shfl_down_sync(0xffffffffu, part, off);

    float score = 0.f;
    if (lane == 0)
        score = part + start_t[yb[0]] + lg[yb[0]] + end_t[yb[L - 1]];

    int j = lane;
    float alpha = (j < CC) ? (start_t[j] + lg[j]) : -INFINITY;
    for (int t = 1; t < L; t++) {
        if (j < CC) alpha_s[j] = alpha;
        __syncwarp();
        float na = alpha;
        if (j < CC) {
            float m = -INFINITY;
#pragma unroll
            for (int i = 0; i < CC; i++)
                m = fmaxf(m, alpha_s[i] + trans_s[i * CC + j]);
            float sum = 0.f;
#pragma unroll
            for (int i = 0; i < CC; i++)
                sum += expf(alpha_s[i] + trans_s[i * CC + j] - m);
            na = m + logf(sum) + lg[t * CC + j];
        }
        __syncwarp();
        alpha = na;
    }

    if (j < CC) alpha_s[j] = alpha + end_t[j];
    __syncwarp();
    if (lane == 0) {
        float m = -INFINITY;
        for (int i = 0; i < CC; i++) m = fmaxf(m, alpha_s[i]);
        float sum = 0.f;
        for (int i = 0; i < CC; i++) sum += expf(alpha_s[i] - m);
        float logZ = m + logf(sum);
        g_llh[b] = score - logZ;
    }
}

// ---------------- kernel 5: loss = -sum_b llh[b] ----------------
__global__ __launch_bounds__(32)
void finalize_kernel(float* __restrict__ out)
{
    int lane = threadIdx.x;
    float v = g_llh[lane];
#pragma unroll
    for (int off = 16; off; off >>= 1)
        v += __shfl_down_sync(0xffffffffu, v, off);
    if (lane == 0) out[0] = -v;
}

// ---------------- launch ----------------
extern "C" void kernel_launch(void* const* d_in, const int* in_sizes, int n_in,
                              void* d_out, int out_size)
{
    (void)in_sizes; (void)n_in; (void)out_size;
    const int*   x       = (const int*)  d_in[0];
    const int*   seq_len = (const int*)  d_in[1];
    const int*   y       = (const int*)  d_in[2];
    // d_in[3] = mask (derived from seq_len instead)
    const float* emb     = (const float*)d_in[4];
    const float* Wih_f   = (const float*)d_in[5];
    const float* Whh_f   = (const float*)d_in[6];
    const float* b_f     = (const float*)d_in[7];
    const float* Wih_b   = (const float*)d_in[8];
    const float* Whh_b   = (const float*)d_in[9];
    const float* b_b     = (const float*)d_in[10];
    const float* W_fc    = (const float*)d_in[11];
    const float* start_t = (const float*)d_in[12];
    const float* end_t   = (const float*)d_in[13];
    const float* trans   = (const float*)d_in[14];
    float* out = (float*)d_out;

    // scan dynamic SMEM: Ws 32KB + hs 32KB + pbuf 16KB = 80KB
    const int scan_smem = (2 * 256 * 32 + 4 * 32 * 32) * (int)sizeof(float);
    static int smem_set = 0;
    if (!smem_set) {
        cudaFuncSetAttribute(lstm_scan2,
                             cudaFuncAttributeMaxDynamicSharedMemorySize, scan_smem);
        smem_set = 1;
    }

    setup_kernel<<<1, 256>>>(seq_len);

    dim3 ggrid(GG / 128, MM / 128);
    gemm_xp<<<ggrid, 256>>>(x, seq_len, emb, Wih_f, b_f, 0);
    gemm_xp<<<ggrid, 256>>>(x, seq_len, emb, Wih_b, b_b, 1);

    lstm_scan2<<<64, 256, scan_smem>>>(Whh_f, Whh_b);

    logits_kernel<<<MM, 256>>>(seq_len, W_fc);

    crf_kernel<<<BB, 32>>>(seq_len, y, start_t, end_t, trans);

    finalize_kernel<<<1, 32>>>(out);
}

// round 9
// speedup vs baseline: 1.7519x; 1.0695x over previous
#include <cuda_runtime.h>
#include <math.h>
#include <stdint.h>

// Problem constants
#define BB 32
#define TT 512
#define EE 256
#define HH 256
#define GG 1024          // 4*H
#define CC 20
#define MM (BB * TT)     // 16384

typedef unsigned long long ull;

// ---------------- f32x2 packed helpers (Blackwell) ----------------
__device__ __forceinline__ ull dup_f32(float x) {
    ull r;
    asm("mov.b64 %0, {%1, %1};" : "=l"(r) : "f"(x));
    return r;
}
__device__ __forceinline__ ull pack_f32(float lo, float hi) {
    ull r;
    asm("mov.b64 %0, {%1, %2};" : "=l"(r) : "f"(lo), "f"(hi));
    return r;
}
__device__ __forceinline__ void ffma2(ull& acc, ull a, ull b) {
    asm("fma.rn.f32x2 %0, %1, %2, %0;" : "+l"(acc) : "l"(a), "l"(b));
}
__device__ __forceinline__ float2 unpack_f32(ull v) {
    float lo, hi;
    asm("mov.b64 {%0, %1}, %2;" : "=f"(lo), "=f"(hi) : "l"(v));
    return make_float2(lo, hi);
}

// ---------------- device scratch (allocation-free rule: static __device__) --------------
__device__ float g_xp_f[(size_t)MM * GG];   // 64 MB
__device__ float g_xp_b[(size_t)MM * GG];   // 64 MB
__device__ float g_out_f[(size_t)MM * HH];  // 16 MB
__device__ float g_out_b[(size_t)MM * HH];  // 16 MB
__device__ float g_logits[(size_t)MM * CC];
__device__ float g_llh[BB];

// persistent-scan state
__device__ float    g_h[2][2][HH][BB];      // [dir][parity][j][b_sorted]
__device__ unsigned g_bar4[2][4];           // 4 split arrival counters per direction
__device__ int      g_perm[BB];             // sorted(batch) -> original batch
__device__ int      g_Lsorted[BB];          // lengths, descending
__device__ int      g_Lmax;

// GEMM compaction
__device__ int   g_rows[MM];                // packed (b<<16)|t for t < seq_len[b]
__device__ int   g_nrows;

// ---------------- kernel 0: setup ----------------
__global__ __launch_bounds__(256)
void setup_kernel(const int* __restrict__ seq_len)
{
    __shared__ int off_s[BB + 1];
    int tid = threadIdx.x;

    // zero h buffers (2*2*256*32 = 32768 floats)
    for (int i = tid; i < 2 * 2 * HH * BB; i += 256)
        (&g_h[0][0][0][0])[i] = 0.f;

    if (tid == 0) {
        int L[BB], p[BB];
        for (int i = 0; i < BB; i++) { L[i] = seq_len[i]; p[i] = i; }
        // stable insertion sort, descending by L
        for (int i = 1; i < BB; i++) {
            int kl = L[i], kp = p[i];
            int j = i - 1;
            while (j >= 0 && L[j] < kl) { L[j + 1] = L[j]; p[j + 1] = p[j]; j--; }
            L[j + 1] = kl; p[j + 1] = kp;
        }
        for (int i = 0; i < BB; i++) { g_perm[i] = p[i]; g_Lsorted[i] = L[i]; }
        g_Lmax = L[0];
        for (int d = 0; d < 2; d++)
            for (int q = 0; q < 4; q++) g_bar4[d][q] = 0u;
        // prefix offsets in ORIGINAL batch order for row compaction
        int off = 0;
        for (int b = 0; b < BB; b++) { off_s[b] = off; off += seq_len[b]; }
        off_s[BB] = off;
        g_nrows = off;
    }
    __syncthreads();

    // fill compacted row list: thread group (b, r) writes rows t = r, r+8, ...
    int b = tid >> 3, r = tid & 7;
    int off = off_s[b];
    int L = off_s[b + 1] - off;
    for (int t = r; t < L; t += 8)
        g_rows[off + t] = (b << 16) | t;
}

// ---------------- kernel 1: xp = gather(emb, x[, reversed]) @ Wih^T + bias -------------
// Compacted M (only t < seq_len rows). Tile 128x128, BK=8, 256 threads, 8x8 per thread,
// f32x2 packed FMA inner loop.
__global__ __launch_bounds__(256)
void gemm_xp(const int* __restrict__ x, const int* __restrict__ seq_len,
             const float* __restrict__ emb, const float* __restrict__ Wih,
             const float* __restrict__ bias, int rev)
{
    const int BM = 128, BN = 128, BK = 8;
    __shared__ float As[BK][BM];
    __shared__ float Bs[BK][BN];
    __shared__ int tok[BM];
    __shared__ int orow[BM];

    int nrows = g_nrows;
    int m0 = blockIdx.y * BM;
    if (m0 >= nrows) return;

    float* __restrict__ xp = rev ? g_xp_b : g_xp_f;

    int tid = threadIdx.x;                 // 256
    int n0 = blockIdx.x * BN;

    if (tid < BM) {
        int m = m0 + tid;
        if (m < nrows) {
            int pk = g_rows[m];
            int b = pk >> 16, t = pk & 0xFFFF;
            int tp = rev ? (seq_len[b] - 1 - t) : t;   // t < L by construction
            tok[tid]  = x[b * TT + tp];
            orow[tid] = b * TT + t;
        } else {
            tok[tid] = 0;
            orow[tid] = -1;
        }
    }
    __syncthreads();

    int tx = tid & 15, ty = tid >> 4;
    int am = tid >> 1, ak = (tid & 1) * 4;
    int bn = tid >> 1, bk = (tid & 1) * 4;

    ull acc2[8][4];
#pragma unroll
    for (int i = 0; i < 8; i++)
#pragma unroll
        for (int j = 0; j < 4; j++) acc2[i][j] = 0ull;

    for (int k0 = 0; k0 < EE; k0 += BK) {
        float4 av = *reinterpret_cast<const float4*>(
            &emb[(size_t)tok[am] * EE + k0 + ak]);
        float4 bv = *reinterpret_cast<const float4*>(
            &Wih[(size_t)(n0 + bn) * EE + k0 + bk]);
        __syncthreads();   // previous tile fully consumed
        As[ak + 0][am] = av.x; As[ak + 1][am] = av.y;
        As[ak + 2][am] = av.z; As[ak + 3][am] = av.w;
        Bs[bk + 0][bn] = bv.x; Bs[bk + 1][bn] = bv.y;
        Bs[bk + 2][bn] = bv.z; Bs[bk + 3][bn] = bv.w;
        __syncthreads();

#pragma unroll
        for (int kk = 0; kk < BK; kk++) {
            float a[8], b[8];
            *reinterpret_cast<float4*>(&a[0]) =
                *reinterpret_cast<const float4*>(&As[kk][ty * 8]);
            *reinterpret_cast<float4*>(&a[4]) =
                *reinterpret_cast<const float4*>(&As[kk][ty * 8 + 4]);
            *reinterpret_cast<float4*>(&b[0]) =
                *reinterpret_cast<const float4*>(&Bs[kk][tx * 8]);
            *reinterpret_cast<float4*>(&b[4]) =
                *reinterpret_cast<const float4*>(&Bs[kk][tx * 8 + 4]);
            ull bp[4];
#pragma unroll
            for (int j = 0; j < 4; j++) bp[j] = pack_f32(b[2 * j], b[2 * j + 1]);
#pragma unroll
            for (int i = 0; i < 8; i++) {
                ull ai = dup_f32(a[i]);
#pragma unroll
                for (int j = 0; j < 4; j++) ffma2(acc2[i][j], ai, bp[j]);
            }
        }
    }

    float bj[8];
#pragma unroll
    for (int j = 0; j < 8; j++) bj[j] = bias[n0 + tx * 8 + j];
#pragma unroll
    for (int i = 0; i < 8; i++) {
        int om = orow[ty * 8 + i];
        if (om >= 0) {
            size_t row = (size_t)om * GG + n0 + tx * 8;
            float2 p0 = unpack_f32(acc2[i][0]);
            float2 p1 = unpack_f32(acc2[i][1]);
            float2 p2 = unpack_f32(acc2[i][2]);
            float2 p3 = unpack_f32(acc2[i][3]);
            float4 v0, v1;
            v0.x = p0.x + bj[0]; v0.y = p0.y + bj[1];
            v0.z = p1.x + bj[2]; v0.w = p1.y + bj[3];
            v1.x = p2.x + bj[4]; v1.y = p2.y + bj[5];
            v1.z = p3.x + bj[6]; v1.w = p3.y + bj[7];
            *reinterpret_cast<float4*>(&xp[row]) = v0;
            *reinterpret_cast<float4*>(&xp[row + 4]) = v1;
        }
    }
}

// ---------------- kernel 2: persistent batched LSTM scan (R5 layout + f32x2 + fast bar)
// 64 CTAs total: dir = bid>>5, ci = bid&31. CTA owns hidden units j in [ci*8, ci*8+8)
// (32 gate rows, 32KB of Whh in SMEM, k-major, for the entire scan).
// Per step: tiny GEMM (32 rows x A batches x 256 k) from SMEM (4x4 micro-tile as
// 4x2 f32x2, 4 k-slices reduced via pbuf), cell update, h exchange through g_h
// (double-buffered) + release/acquire 4-way-split counter grid barrier per direction.
__global__ __launch_bounds__(256)
void lstm_scan2(const float* __restrict__ Whh_f, const float* __restrict__ Whh_b)
{
    extern __shared__ float sm[];
    float* Ws   = sm;                    // [256][32]  Ws[k*32 + lrow]
    float* hs   = sm + 256 * 32;         // [256][32]  hs[k*32 + b]
    float* pbuf = sm + 2 * 256 * 32;     // [4][32][32] pbuf[(s*32+r)*32 + b]
    __shared__ int perm_s[BB];
    __shared__ int Ls[BB];

    int dir = blockIdx.x >> 5;
    int ci  = blockIdx.x & 31;
    int tid = threadIdx.x;

    const float* __restrict__ xp  = dir ? g_xp_b : g_xp_f;
    const float* __restrict__ Whh = dir ? Whh_b : Whh_f;
    float* __restrict__ out       = dir ? g_out_b : g_out_f;

    if (tid < BB) { perm_s[tid] = g_perm[tid]; Ls[tid] = g_Lsorted[tid]; }
    int Lmax = g_Lmax;

    // ---- fill weight slice into SMEM, k-major: Ws[k][lrow], lrow = q*8+u ----
    for (int i = tid; i < 32 * 64; i += 256) {
        int lrow = i & 31, k4 = i >> 5;
        int q = lrow >> 3, u = lrow & 7;
        int grow = q * 256 + ci * 8 + u;
        float4 w = *reinterpret_cast<const float4*>(&Whh[(size_t)grow * 256 + k4 * 4]);
        Ws[(k4 * 4 + 0) * 32 + lrow] = w.x;
        Ws[(k4 * 4 + 1) * 32 + lrow] = w.y;
        Ws[(k4 * 4 + 2) * 32 + lrow] = w.z;
        Ws[(k4 * 4 + 3) * 32 + lrow] = w.w;
    }
    __syncthreads();

    // GEMM roles: k-slice s (64 k each), 8 row-groups x 8 batch-groups, 4x4 micro-tile
    int s    = tid >> 6;
    int s64  = tid & 63;
    int rowg = s64 & 7;
    int bg   = s64 >> 3;
    // cell roles: tid = b_cell*8 + u_cell
    int b_cell = tid >> 3;
    int u_cell = tid & 7;

    float c_state = 0.f;
    int A = BB;

    const float4* W4 = reinterpret_cast<const float4*>(Ws);  // [k][8] float4
    const float4* H4 = reinterpret_cast<const float4*>(hs);

    unsigned* barp = &g_bar4[dir][0];

    for (int t = 0; t < Lmax; t++) {
        while (A > 0 && Ls[A - 1] <= t) A--;
        int pw = t & 1, pr = pw ^ 1;
        int nb4 = (A + 3) >> 2;   // active float4 batch-groups

        // ---- fill hs from g_h[dir][pr], active columns only ----
        {
            const float4* src = reinterpret_cast<const float4*>(&g_h[dir][pr][0][0]);
            float4* dst = reinterpret_cast<float4*>(hs);
            for (int i = tid; i < 2048; i += 256)
                if ((i & 7) < nb4) dst[i] = src[i];
        }

        // ---- prefetch this thread's xp gate values (cell role) ----
        int Lb = Ls[b_cell];
        bool act = (t < Lb);
        int ob = perm_s[b_cell];
        float xg0 = 0.f, xg1 = 0.f, xg2 = 0.f, xg3 = 0.f;
        if (act) {
            size_t xbase = ((size_t)ob * TT + t) * GG + (size_t)ci * 8 + u_cell;
            xg0 = xp[xbase];
            xg1 = xp[xbase + 256];
            xg2 = xp[xbase + 512];
            xg3 = xp[xbase + 768];
        }
        __syncthreads();   // hs ready; pbuf from previous step fully consumed

        // ---- micro-GEMM: gates[row][b] partial over k-slice s (f32x2 packed) ----
        ull acc2[4][2];
#pragma unroll
        for (int i = 0; i < 4; i++) { acc2[i][0] = 0ull; acc2[i][1] = 0ull; }

        if (bg * 4 < A) {
            int kbase = s * 64;
#pragma unroll 8
            for (int k = 0; k < 64; k++) {
                float4 wv = W4[(kbase + k) * 8 + rowg];
                float4 hv = H4[(kbase + k) * 8 + bg];
                ull h01 = pack_f32(hv.x, hv.y);
                ull h23 = pack_f32(hv.z, hv.w);
                ull w;
                w = dup_f32(wv.x); ffma2(acc2[0][0], w, h01); ffma2(acc2[0][1], w, h23);
                w = dup_f32(wv.y); ffma2(acc2[1][0], w, h01); ffma2(acc2[1][1], w, h23);
                w = dup_f32(wv.z); ffma2(acc2[2][0], w, h01); ffma2(acc2[2][1], w, h23);
                w = dup_f32(wv.w); ffma2(acc2[3][0], w, h01); ffma2(acc2[3][1], w, h23);
            }
        }
#pragma unroll
        for (int i = 0; i < 4; i++) {
            float2 p0 = unpack_f32(acc2[i][0]);
            float2 p1 = unpack_f32(acc2[i][1]);
            float* row = &pbuf[(s * 32 + rowg * 4 + i) * 32 + bg * 4];
            row[0] = p0.x; row[1] = p0.y; row[2] = p1.x; row[3] = p1.y;
        }
        __syncthreads();

        // ---- reduce 4 k-slices + cell update + write h/out ----
        if (act) {
            float g4[4];
#pragma unroll
            for (int q = 0; q < 4; q++) {
                int r = q * 8 + u_cell;
                float v = 0.f;
#pragma unroll
                for (int s2 = 0; s2 < 4; s2++)
                    v += pbuf[(s2 * 32 + r) * 32 + b_cell];
                g4[q] = v;
            }
            g4[0] += xg0; g4[1] += xg1; g4[2] += xg2; g4[3] += xg3;
            float i_ = 1.f / (1.f + __expf(-g4[0]));
            float f_ = 1.f / (1.f + __expf(-g4[1]));
            float o_ = 1.f / (1.f + __expf(-g4[3]));
            c_state = f_ * c_state + i_ * tanhf(g4[2]);
            float hv = o_ * tanhf(c_state);
            int j = ci * 8 + u_cell;
            g_h[dir][pw][j][b_cell] = hv;
            out[((size_t)ob * TT + t) * HH + j] = hv;
        }

        // ---- grid barrier (per direction): 4-way split counters, rel/acq ----
        __syncthreads();               // all g_h writes of this CTA done
        if (tid == 0) {
            // release-arrive on counter (ci & 3): cumulative, covers whole CTA
            asm volatile("red.release.gpu.global.add.u32 [%0], %1;"
                         :: "l"(barp + (ci & 3)), "r"(1u) : "memory");
        }
        if (tid < 4) {
            unsigned tgt = 8u * (unsigned)(t + 1);
            unsigned v;
            do {
                asm volatile("ld.acquire.gpu.global.u32 %0, [%1];"
                             : "=r"(v) : "l"(barp + tid) : "memory");
            } while (v < tgt);
        }
        __syncthreads();               // propagate acquire to whole CTA
    }
}

// ---------------- kernel 3: logits = log_softmax(concat(out_f, rev(out_b)) @ W_fc^T) ---
__global__ __launch_bounds__(256)
void logits_kernel(const int* __restrict__ seq_len,
                   const float* __restrict__ W_fc)
{
    int bt = blockIdx.x;
    int b = bt / TT, t = bt % TT;
    int L = seq_len[b];
    if (t >= L) return;

    __shared__ float outs[2 * HH];
    __shared__ float dots[CC];
    __shared__ float lse_s;

    int tid = threadIdx.x;  // 256
    outs[tid]       = g_out_f[(size_t)bt * HH + tid];
    outs[HH + tid]  = g_out_b[(size_t)(b * TT + (L - 1 - t)) * HH + tid];
    __syncthreads();

    int warp = tid >> 5, lane = tid & 31;
    for (int cls = warp; cls < CC; cls += 8) {
        float acc = 0.f;
#pragma unroll 4
        for (int e = lane; e < 2 * HH; e += 32)
            acc += outs[e] * W_fc[cls * (2 * HH) + e];
#pragma unroll
        for (int off = 16; off; off >>= 1)
            acc += __shfl_down_sync(0xffffffffu, acc, off);
        if (lane == 0) dots[cls] = acc;
    }
    __syncthreads();

    if (tid == 0) {
        float m = -INFINITY;
        for (int cI = 0; cI < CC; cI++) m = fmaxf(m, dots[cI]);
        float sum = 0.f;
        for (int cI = 0; cI < CC; cI++) sum += expf(dots[cI] - m);
        lse_s = m + logf(sum);
    }
    __syncthreads();

    if (tid < CC) g_logits[(size_t)bt * CC + tid] = dots[tid] - lse_s;
}

// ---------------- kernel 4: CRF gold score + forward algorithm, warp per batch ----------
__global__ __launch_bounds__(32)
void crf_kernel(const int* __restrict__ seq_len, const int* __restrict__ y,
                const float* __restrict__ start_t, const float* __restrict__ end_t,
                const float* __restrict__ trans)
{
    int b = blockIdx.x;
    int lane = threadIdx.x;  // 32

    __shared__ float trans_s[CC * CC];
    __shared__ float alpha_s[CC];
    for (int i = lane; i < CC * CC; i += 32) trans_s[i] = trans[i];
    __syncwarp();

    int L = seq_len[b];
    const float* lg = g_logits + (size_t)b * TT * CC;
    const int* yb = y + b * TT;

    float part = 0.f;
    for (int t = 1 + lane; t < L; t += 32)
        part += trans_s[yb[t - 1] * CC + yb[t]] + lg[t * CC + yb[t]];
#pragma unroll
    for (int off = 16; off; off >>= 1)
        part += __shfl_down_sync(0xffffffffu, part, off);

    float score = 0.f;
    if (lane == 0)
        score = part + start_t[yb[0]] + lg[yb[0]] + end_t[yb[L - 1]];

    int j = lane;
    float alpha = (j < CC) ? (start_t[j] + lg[j]) : -INFINITY;
    for (int t = 1; t < L; t++) {
        if (j < CC) alpha_s[j] = alpha;
        __syncwarp();
        float na = alpha;
        if (j < CC) {
            float m = -INFINITY;
#pragma unroll
            for (int i = 0; i < CC; i++)
                m = fmaxf(m, alpha_s[i] + trans_s[i * CC + j]);
            float sum = 0.f;
#pragma unroll
            for (int i = 0; i < CC; i++)
                sum += expf(alpha_s[i] + trans_s[i * CC + j] - m);
            na = m + logf(sum) + lg[t * CC + j];
        }
        __syncwarp();
        alpha = na;
    }

    if (j < CC) alpha_s[j] = alpha + end_t[j];
    __syncwarp();
    if (lane == 0) {
        float m = -INFINITY;
        for (int i = 0; i < CC; i++) m = fmaxf(m, alpha_s[i]);
        float sum = 0.f;
        for (int i = 0; i < CC; i++) sum += expf(alpha_s[i] - m);
        float logZ = m + logf(sum);
        g_llh[b] = score - logZ;
    }
}

// ---------------- kernel 5: loss = -sum_b llh[b] ----------------
__global__ __launch_bounds__(32)
void finalize_kernel(float* __restrict__ out)
{
    int lane = threadIdx.x;
    float v = g_llh[lane];
#pragma unroll
    for (int off = 16; off; off >>= 1)
        v += __shfl_down_sync(0xffffffffu, v, off);
    if (lane == 0) out[0] = -v;
}

// ---------------- launch ----------------
extern "C" void kernel_launch(void* const* d_in, const int* in_sizes, int n_in,
                              void* d_out, int out_size)
{
    (void)in_sizes; (void)n_in; (void)out_size;
    const int*   x       = (const int*)  d_in[0];
    const int*   seq_len = (const int*)  d_in[1];
    const int*   y       = (const int*)  d_in[2];
    // d_in[3] = mask (derived from seq_len instead)
    const float* emb     = (const float*)d_in[4];
    const float* Wih_f   = (const float*)d_in[5];
    const float* Whh_f   = (const float*)d_in[6];
    const float* b_f     = (const float*)d_in[7];
    const float* Wih_b   = (const float*)d_in[8];
    const float* Whh_b   = (const float*)d_in[9];
    const float* b_b     = (const float*)d_in[10];
    const float* W_fc    = (const float*)d_in[11];
    const float* start_t = (const float*)d_in[12];
    const float* end_t   = (const float*)d_in[13];
    const float* trans   = (const float*)d_in[14];
    float* out = (float*)d_out;

    // scan dynamic SMEM: Ws 32KB + hs 32KB + pbuf 16KB = 80KB
    const int scan_smem = (2 * 256 * 32 + 4 * 32 * 32) * (int)sizeof(float);
    static int smem_set = 0;
    if (!smem_set) {
        cudaFuncSetAttribute(lstm_scan2,
                             cudaFuncAttributeMaxDynamicSharedMemorySize, scan_smem);
        smem_set = 1;
    }

    setup_kernel<<<1, 256>>>(seq_len);

    dim3 ggrid(GG / 128, MM / 128);
    gemm_xp<<<ggrid, 256>>>(x, seq_len, emb, Wih_f, b_f, 0);
    gemm_xp<<<ggrid, 256>>>(x, seq_len, emb, Wih_b, b_b, 1);

    lstm_scan2<<<64, 256, scan_smem>>>(Whh_f, Whh_b);

    logits_kernel<<<MM, 256>>>(seq_len, W_fc);

    crf_kernel<<<BB, 32>>>(seq_len, y, start_t, end_t, trans);

    finalize_kernel<<<1, 32>>>(out);
}

// round 10
// speedup vs baseline: 2.6532x; 1.5145x over previous
#include <cuda_runtime.h>
#include <math.h>
#include <stdint.h>

// Problem constants
#define BB 32
#define TT 512
#define EE 256
#define HH 256
#define GG 1024          // 4*H
#define CC 20
#define MM (BB * TT)     // 16384

typedef unsigned long long ull;

// ---------------- f32x2 packed helpers (Blackwell) ----------------
__device__ __forceinline__ ull dup_f32(float x) {
    ull r;
    asm("mov.b64 %0, {%1, %1};" : "=l"(r) : "f"(x));
    return r;
}
__device__ __forceinline__ ull pack_f32(float lo, float hi) {
    ull r;
    asm("mov.b64 %0, {%1, %2};" : "=l"(r) : "f"(lo), "f"(hi));
    return r;
}
__device__ __forceinline__ void ffma2(ull& acc, ull a, ull b) {
    asm("fma.rn.f32x2 %0, %1, %2, %0;" : "+l"(acc) : "l"(a), "l"(b));
}
__device__ __forceinline__ float2 unpack_f32(ull v) {
    float lo, hi;
    asm("mov.b64 {%0, %1}, %2;" : "=f"(lo), "=f"(hi) : "l"(v));
    return make_float2(lo, hi);
}

// ---------------- cluster / DSMEM helpers ----------------
__device__ __forceinline__ uint32_t smem_u32(const void* p) {
    uint32_t a;
    asm("{ .reg .u64 t; cvta.to.shared.u64 t, %1; cvt.u32.u64 %0, t; }"
        : "=r"(a) : "l"(p));
    return a;
}
__device__ __forceinline__ void st_cluster_f32(uint32_t local_addr, uint32_t rank, float v) {
    uint32_t ra;
    asm("mapa.shared::cluster.u32 %0, %1, %2;" : "=r"(ra) : "r"(local_addr), "r"(rank));
    asm volatile("st.shared::cluster.f32 [%0], %1;" :: "r"(ra), "f"(v) : "memory");
}
#define CLUSTER_SYNC_() do { \
    asm volatile("barrier.cluster.arrive.aligned;" ::: "memory"); \
    asm volatile("barrier.cluster.wait.aligned;" ::: "memory"); } while (0)

// ---------------- device scratch (allocation-free rule: static __device__) --------------
__device__ float g_xp_f[(size_t)MM * GG];   // 64 MB
__device__ float g_xp_b[(size_t)MM * GG];   // 64 MB
__device__ float g_out_f[(size_t)MM * HH];  // 16 MB
__device__ float g_out_b[(size_t)MM * HH];  // 16 MB
__device__ float g_logits[(size_t)MM * CC];
__device__ float g_llh[BB];

// scan bookkeeping
__device__ int g_perm[BB];                  // sorted(batch) -> original batch
__device__ int g_Lsorted[BB];               // lengths, descending

// GEMM compaction
__device__ int g_rows[MM];                  // packed (b<<16)|t for t < seq_len[b]
__device__ int g_nrows;

// ---------------- kernel 0: setup ----------------
__global__ __launch_bounds__(256)
void setup_kernel(const int* __restrict__ seq_len)
{
    __shared__ int off_s[BB + 1];
    int tid = threadIdx.x;

    if (tid == 0) {
        int L[BB], p[BB];
        for (int i = 0; i < BB; i++) { L[i] = seq_len[i]; p[i] = i; }
        // stable insertion sort, descending by L
        for (int i = 1; i < BB; i++) {
            int kl = L[i], kp = p[i];
            int j = i - 1;
            while (j >= 0 && L[j] < kl) { L[j + 1] = L[j]; p[j + 1] = p[j]; j--; }
            L[j + 1] = kl; p[j + 1] = kp;
        }
        for (int i = 0; i < BB; i++) { g_perm[i] = p[i]; g_Lsorted[i] = L[i]; }
        // prefix offsets in ORIGINAL batch order for row compaction
        int off = 0;
        for (int b = 0; b < BB; b++) { off_s[b] = off; off += seq_len[b]; }
        off_s[BB] = off;
        g_nrows = off;
    }
    __syncthreads();

    // fill compacted row list: thread group (b, r) writes rows t = r, r+8, ...
    int b = tid >> 3, r = tid & 7;
    int off = off_s[b];
    int L = off_s[b + 1] - off;
    for (int t = r; t < L; t += 8)
        g_rows[off + t] = (b << 16) | t;
}

// ---------------- kernel 1: xp = gather(emb, x[, reversed]) @ Wih^T + bias -------------
// Compacted M (only t < seq_len rows). Tile 128x128, BK=8, 256 threads, 8x8 per thread,
// f32x2 packed FMA inner loop.
__global__ __launch_bounds__(256)
void gemm_xp(const int* __restrict__ x, const int* __restrict__ seq_len,
             const float* __restrict__ emb, const float* __restrict__ Wih,
             const float* __restrict__ bias, int rev)
{
    const int BM = 128, BN = 128, BK = 8;
    __shared__ float As[BK][BM];
    __shared__ float Bs[BK][BN];
    __shared__ int tok[BM];
    __shared__ int orow[BM];

    int nrows = g_nrows;
    int m0 = blockIdx.y * BM;
    if (m0 >= nrows) return;

    float* __restrict__ xp = rev ? g_xp_b : g_xp_f;

    int tid = threadIdx.x;                 // 256
    int n0 = blockIdx.x * BN;

    if (tid < BM) {
        int m = m0 + tid;
        if (m < nrows) {
            int pk = g_rows[m];
            int b = pk >> 16, t = pk & 0xFFFF;
            int tp = rev ? (seq_len[b] - 1 - t) : t;   // t < L by construction
            tok[tid]  = x[b * TT + tp];
            orow[tid] = b * TT + t;
        } else {
            tok[tid] = 0;
            orow[tid] = -1;
        }
    }
    __syncthreads();

    int tx = tid & 15, ty = tid >> 4;
    int am = tid >> 1, ak = (tid & 1) * 4;
    int bn = tid >> 1, bk = (tid & 1) * 4;

    ull acc2[8][4];
#pragma unroll
    for (int i = 0; i < 8; i++)
#pragma unroll
        for (int j = 0; j < 4; j++) acc2[i][j] = 0ull;

    for (int k0 = 0; k0 < EE; k0 += BK) {
        float4 av = *reinterpret_cast<const float4*>(
            &emb[(size_t)tok[am] * EE + k0 + ak]);
        float4 bv = *reinterpret_cast<const float4*>(
            &Wih[(size_t)(n0 + bn) * EE + k0 + bk]);
        __syncthreads();   // previous tile fully consumed
        As[ak + 0][am] = av.x; As[ak + 1][am] = av.y;
        As[ak + 2][am] = av.z; As[ak + 3][am] = av.w;
        Bs[bk + 0][bn] = bv.x; Bs[bk + 1][bn] = bv.y;
        Bs[bk + 2][bn] = bv.z; Bs[bk + 3][bn] = bv.w;
        __syncthreads();

#pragma unroll
        for (int kk = 0; kk < BK; kk++) {
            float a[8], b[8];
            *reinterpret_cast<float4*>(&a[0]) =
                *reinterpret_cast<const float4*>(&As[kk][ty * 8]);
            *reinterpret_cast<float4*>(&a[4]) =
                *reinterpret_cast<const float4*>(&As[kk][ty * 8 + 4]);
            *reinterpret_cast<float4*>(&b[0]) =
                *reinterpret_cast<const float4*>(&Bs[kk][tx * 8]);
            *reinterpret_cast<float4*>(&b[4]) =
                *reinterpret_cast<const float4*>(&Bs[kk][tx * 8 + 4]);
            ull bp[4];
#pragma unroll
            for (int j = 0; j < 4; j++) bp[j] = pack_f32(b[2 * j], b[2 * j + 1]);
#pragma unroll
            for (int i = 0; i < 8; i++) {
                ull ai = dup_f32(a[i]);
#pragma unroll
                for (int j = 0; j < 4; j++) ffma2(acc2[i][j], ai, bp[j]);
            }
        }
    }

    float bj[8];
#pragma unroll
    for (int j = 0; j < 8; j++) bj[j] = bias[n0 + tx * 8 + j];
#pragma unroll
    for (int i = 0; i < 8; i++) {
        int om = orow[ty * 8 + i];
        if (om >= 0) {
            size_t row = (size_t)om * GG + n0 + tx * 8;
            float2 p0 = unpack_f32(acc2[i][0]);
            float2 p1 = unpack_f32(acc2[i][1]);
            float2 p2 = unpack_f32(acc2[i][2]);
            float2 p3 = unpack_f32(acc2[i][3]);
            float4 v0, v1;
            v0.x = p0.x + bj[0]; v0.y = p0.y + bj[1];
            v0.z = p1.x + bj[2]; v0.w = p1.y + bj[3];
            v1.x = p2.x + bj[4]; v1.y = p2.y + bj[5];
            v1.z = p3.x + bj[6]; v1.w = p3.y + bj[7];
            *reinterpret_cast<float4*>(&xp[row]) = v0;
            *reinterpret_cast<float4*>(&xp[row + 4]) = v1;
        }
    }
}

// ---------------- kernel 2: clustered LSTM scan (DSMEM h-exchange) ----------------------
// 128 CTAs = 16 clusters x 8. cluster cid: dir = cid&1, grp = cid>>1 (4 sorted batches).
// CTA rank owns hidden units [rank*32, rank*32+32) -> 128 gate rows of Whh (128KB) in
// SMEM for the whole scan. Per step: 128row x 4batch x 256k micro-GEMM from SMEM,
// cell update, h pushed to all 8 CTAs' SMEM via st.shared::cluster, ONE cluster barrier.
__global__ __launch_bounds__(256) __cluster_dims__(8, 1, 1)
void lstm_scan4(const float* __restrict__ Whh_f, const float* __restrict__ Whh_b)
{
    extern __shared__ float sm[];
    float* Ws   = sm;                       // [256][128]  Ws[k*128 + lrow], lrow = q*32+u
    float* hs0  = sm + 256 * 128;           // [256][4]    h buffer parity 0
    float* hs1  = hs0 + 256 * 4;            // [256][4]    h buffer parity 1
    float* pbuf = hs1 + 256 * 4;            // [8][128][4] k-slice partials

    int bid  = blockIdx.x;
    int cid  = bid >> 3;
    int rank = bid & 7;
    int dir  = cid & 1;
    int grp  = cid >> 1;
    int tid  = threadIdx.x;

    const float* __restrict__ xp  = dir ? g_xp_b : g_xp_f;
    const float* __restrict__ Whh = dir ? Whh_b : Whh_f;
    float* __restrict__ out       = dir ? g_out_b : g_out_f;

    __shared__ int perm_s[4];
    __shared__ int Ls_s[4];
    if (tid < 4) {
        perm_s[tid] = g_perm[grp * 4 + tid];
        Ls_s[tid]   = g_Lsorted[grp * 4 + tid];
    }
    int Lmax = g_Lsorted[grp * 4];          // group sorted desc -> first is longest

    // ---- load this CTA's 128 gate rows of Whh into SMEM, k-major ----
    for (int i = tid; i < 128 * 64; i += 256) {
        int lrow = i & 127, k4 = i >> 7;
        int q = lrow >> 5, u = lrow & 31;
        int grow = q * 256 + rank * 32 + u;
        float4 w = *reinterpret_cast<const float4*>(&Whh[(size_t)grow * 256 + k4 * 4]);
        Ws[(k4 * 4 + 0) * 128 + lrow] = w.x;
        Ws[(k4 * 4 + 1) * 128 + lrow] = w.y;
        Ws[(k4 * 4 + 2) * 128 + lrow] = w.z;
        Ws[(k4 * 4 + 3) * 128 + lrow] = w.w;
    }
    __syncthreads();
    CLUSTER_SYNC_();   // all SMEM ready before any DSMEM pushes

    // GEMM roles: s = k-slice (8 x 32k), rowg = 4-row group (32)
    int s    = tid >> 5;
    int rowg = tid & 31;
    // cell roles (tid < 128): b_cell 0..3, u_cell 0..31
    int b_cell = tid >> 5;   // only valid for tid < 128
    int u_cell = tid & 31;
    int j_cell = rank * 32 + u_cell;

    uint32_t hs0_a = smem_u32(hs0);
    uint32_t hs1_a = smem_u32(hs1);

    const float4* W4 = reinterpret_cast<const float4*>(Ws);
    float4* P4 = reinterpret_cast<float4*>(pbuf);

    float c_state = 0.f;

    for (int t = 0; t < Lmax; t++) {
        int pr = t & 1;
        const float4* H4 = reinterpret_cast<const float4*>(pr ? hs1 : hs0);
        uint32_t hsw_a = pr ? hs0_a : hs1_a;   // write opposite parity

        // ---- prefetch xp gate values (cell threads) ----
        bool cellth = tid < 128;
        bool act = false;
        int ob = 0;
        float xg0 = 0.f, xg1 = 0.f, xg2 = 0.f, xg3 = 0.f;
        if (cellth) {
            act = (t < Ls_s[b_cell]);
            if (act) {
                ob = perm_s[b_cell];
                size_t xb = ((size_t)ob * TT + t) * GG + (size_t)rank * 32 + u_cell;
                xg0 = xp[xb];
                xg1 = xp[xb + 256];
                xg2 = xp[xb + 512];
                xg3 = xp[xb + 768];
            }
        }

        // ---- micro-GEMM over k-slice s (32 k), rows rowg*4..+4, all 4 batches ----
        if (t > 0) {
            ull acc2[4][2];
#pragma unroll
            for (int i = 0; i < 4; i++) { acc2[i][0] = 0ull; acc2[i][1] = 0ull; }
            int kbase = s * 32;
#pragma unroll 8
            for (int k = 0; k < 32; k++) {
                float4 wv = W4[(kbase + k) * 32 + rowg];
                float4 hv = H4[kbase + k];
                ull h01 = pack_f32(hv.x, hv.y);
                ull h23 = pack_f32(hv.z, hv.w);
                ull w;
                w = dup_f32(wv.x); ffma2(acc2[0][0], w, h01); ffma2(acc2[0][1], w, h23);
                w = dup_f32(wv.y); ffma2(acc2[1][0], w, h01); ffma2(acc2[1][1], w, h23);
                w = dup_f32(wv.z); ffma2(acc2[2][0], w, h01); ffma2(acc2[2][1], w, h23);
                w = dup_f32(wv.w); ffma2(acc2[3][0], w, h01); ffma2(acc2[3][1], w, h23);
            }
#pragma unroll
            for (int i = 0; i < 4; i++) {
                float2 p0 = unpack_f32(acc2[i][0]);
                float2 p1 = unpack_f32(acc2[i][1]);
                float4 v; v.x = p0.x; v.y = p0.y; v.z = p1.x; v.w = p1.y;
                P4[s * 128 + rowg * 4 + i] = v;
            }
        }
        __syncthreads();

        // ---- reduce 8 k-slices + cell update + DSMEM push ----
        if (cellth && act) {
            float g0 = xg0, g1 = xg1, g2 = xg2, g3 = xg3;
            if (t > 0) {
#pragma unroll
                for (int s2 = 0; s2 < 8; s2++) {
                    const float* pb = &pbuf[(size_t)(s2 * 128) * 4 + b_cell];
                    g0 += pb[(0 * 32 + u_cell) * 4];
                    g1 += pb[(1 * 32 + u_cell) * 4];
                    g2 += pb[(2 * 32 + u_cell) * 4];
                    g3 += pb[(3 * 32 + u_cell) * 4];
                }
            }
            float i_ = 1.f / (1.f + __expf(-g0));
            float f_ = 1.f / (1.f + __expf(-g1));
            float o_ = 1.f / (1.f + __expf(-g3));
            c_state = f_ * c_state + i_ * tanhf(g2);
            float hv = o_ * tanhf(c_state);

            uint32_t off = hsw_a + (uint32_t)(j_cell * 4 + b_cell) * 4u;
#pragma unroll
            for (int r = 0; r < 8; r++) st_cluster_f32(off, r, hv);

            out[((size_t)ob * TT + t) * HH + j_cell] = hv;
        }

        // ---- one cluster barrier per step (orders DSMEM pushes + parity swap) ----
        CLUSTER_SYNC_();
    }
}

// ---------------- kernel 3: logits = log_softmax(concat(out_f, rev(out_b)) @ W_fc^T) ---
__global__ __launch_bounds__(256)
void logits_kernel(const int* __restrict__ seq_len,
                   const float* __restrict__ W_fc)
{
    int bt = blockIdx.x;
    int b = bt / TT, t = bt % TT;
    int L = seq_len[b];
    if (t >= L) return;

    __shared__ float outs[2 * HH];
    __shared__ float dots[CC];
    __shared__ float lse_s;

    int tid = threadIdx.x;  // 256
    outs[tid]       = g_out_f[(size_t)bt * HH + tid];
    outs[HH + tid]  = g_out_b[(size_t)(b * TT + (L - 1 - t)) * HH + tid];
    __syncthreads();

    int warp = tid >> 5, lane = tid & 31;
    for (int cls = warp; cls < CC; cls += 8) {
        float acc = 0.f;
#pragma unroll 4
        for (int e = lane; e < 2 * HH; e += 32)
            acc += outs[e] * W_fc[cls * (2 * HH) + e];
#pragma unroll
        for (int off = 16; off; off >>= 1)
            acc += __shfl_down_sync(0xffffffffu, acc, off);
        if (lane == 0) dots[cls] = acc;
    }
    __syncthreads();

    if (tid == 0) {
        float m = -INFINITY;
        for (int cI = 0; cI < CC; cI++) m = fmaxf(m, dots[cI]);
        float sum = 0.f;
        for (int cI = 0; cI < CC; cI++) sum += expf(dots[cI] - m);
        lse_s = m + logf(sum);
    }
    __syncthreads();

    if (tid < CC) g_logits[(size_t)bt * CC + tid] = dots[tid] - lse_s;
}

// ---------------- kernel 4: CRF gold score + forward algorithm, warp per batch ----------
__global__ __launch_bounds__(32)
void crf_kernel(const int* __restrict__ seq_len, const int* __restrict__ y,
                const float* __restrict__ start_t, const float* __restrict__ end_t,
                const float* __restrict__ trans)
{
    int b = blockIdx.x;
    int lane = threadIdx.x;  // 32

    __shared__ float trans_s[CC * CC];
    __shared__ float alpha_s[CC];
    for (int i = lane; i < CC * CC; i += 32) trans_s[i] = trans[i];
    __syncwarp();

    int L = seq_len[b];
    const float* lg = g_logits + (size_t)b * TT * CC;
    const int* yb = y + b * TT;

    float part = 0.f;
    for (int t = 1 + lane; t < L; t += 32)
        part += trans_s[yb[t - 1] * CC + yb[t]] + lg[t * CC + yb[t]];
#pragma unroll
    for (int off = 16; off; off >>= 1)
        part += __shfl_down_sync(0xffffffffu, part, off);

    float score = 0.f;
    if (lane == 0)
        score = part + start_t[yb[0]] + lg[yb[0]] + end_t[yb[L - 1]];

    int j = lane;
    float alpha = (j < CC) ? (start_t[j] + lg[j]) : -INFINITY;
    for (int t = 1; t < L; t++) {
        if (j < CC) alpha_s[j] = alpha;
        __syncwarp();
        float na = alpha;
        if (j < CC) {
            float m = -INFINITY;
#pragma unroll
            for (int i = 0; i < CC; i++)
                m = fmaxf(m, alpha_s[i] + trans_s[i * CC + j]);
            float sum = 0.f;
#pragma unroll
            for (int i = 0; i < CC; i++)
                sum += expf(alpha_s[i] + trans_s[i * CC + j] - m);
            na = m + logf(sum) + lg[t * CC + j];
        }
        __syncwarp();
        alpha = na;
    }

    if (j < CC) alpha_s[j] = alpha + end_t[j];
    __syncwarp();
    if (lane == 0) {
        float m = -INFINITY;
        for (int i = 0; i < CC; i++) m = fmaxf(m, alpha_s[i]);
        float sum = 0.f;
        for (int i = 0; i < CC; i++) sum += expf(alpha_s[i] - m);
        float logZ = m + logf(sum);
        g_llh[b] = score - logZ;
    }
}

// ---------------- kernel 5: loss = -sum_b llh[b] ----------------
__global__ __launch_bounds__(32)
void finalize_kernel(float* __restrict__ out)
{
    int lane = threadIdx.x;
    float v = g_llh[lane];
#pragma unroll
    for (int off = 16; off; off >>= 1)
        v += __shfl_down_sync(0xffffffffu, v, off);
    if (lane == 0) out[0] = -v;
}

// ---------------- launch ----------------
extern "C" void kernel_launch(void* const* d_in, const int* in_sizes, int n_in,
                              void* d_out, int out_size)
{
    (void)in_sizes; (void)n_in; (void)out_size;
    const int*   x       = (const int*)  d_in[0];
    const int*   seq_len = (const int*)  d_in[1];
    const int*   y       = (const int*)  d_in[2];
    // d_in[3] = mask (derived from seq_len instead)
    const float* emb     = (const float*)d_in[4];
    const float* Wih_f   = (const float*)d_in[5];
    const float* Whh_f   = (const float*)d_in[6];
    const float* b_f     = (const float*)d_in[7];
    const float* Wih_b   = (const float*)d_in[8];
    const float* Whh_b   = (const float*)d_in[9];
    const float* b_b     = (const float*)d_in[10];
    const float* W_fc    = (const float*)d_in[11];
    const float* start_t = (const float*)d_in[12];
    const float* end_t   = (const float*)d_in[13];
    const float* trans   = (const float*)d_in[14];
    float* out = (float*)d_out;

    // scan dynamic SMEM: Ws 128KB + hs 2x4KB + pbuf 16KB = 152KB
    const int scan_smem = (256 * 128 + 2 * 256 * 4 + 8 * 128 * 4) * (int)sizeof(float);
    static int smem_set = 0;
    if (!smem_set) {
        cudaFuncSetAttribute(lstm_scan4,
                             cudaFuncAttributeMaxDynamicSharedMemorySize, scan_smem);
        smem_set = 1;
    }

    setup_kernel<<<1, 256>>>(seq_len);

    dim3 ggrid(GG / 128, MM / 128);
    gemm_xp<<<ggrid, 256>>>(x, seq_len, emb, Wih_f, b_f, 0);
    gemm_xp<<<ggrid, 256>>>(x, seq_len, emb, Wih_b, b_b, 1);

    lstm_scan4<<<128, 256, scan_smem>>>(Whh_f, Whh_b);

    logits_kernel<<<MM, 256>>>(seq_len, W_fc);

    crf_kernel<<<BB, 32>>>(seq_len, y, start_t, end_t, trans);

    finalize_kernel<<<1, 32>>>(out);
}